// round 2
// baseline (speedup 1.0000x reference)
#include <cuda_runtime.h>
#include <cstdint>

// Problem constants
#define BB   2048
#define LL   128
#define VV   128
#define EE   32
#define DD   64
#define NCB  10

// Output layout (concatenated, float32)
#define OFF_PUZZ  33554432
#define OFF_FEAT  35397632
#define OFF_QST   153362432
#define OFF_LOSS  271327232

// Scratch (no allocation allowed)
__device__ int   g_codes[BB * 30];
__device__ float g_partial[BB];
__device__ float g_enc[BB * 30 * DD];     // encoder output rows [B][30][64]

// ---------------- Encoder shared layout (floats) ----------------
// SA  (4224): X [32][132] during gather/conv1; then H2 [64][32] @0 + ENC [30][64] @2048
// H1  (4224): [64][66]
// WB  (6144): weight staging (w1 full; w2/w3 in e-halves)
// CB  (640), DIST (304), BS (64)
#define ENC_SA   0
#define ENC_H1   4224
#define ENC_WB   8448
#define ENC_CB   14592
#define ENC_DIST 15232
#define ENC_BS   15536
#define ENC_SMEM_FLOATS 15600
#define ENC_SMEM_BYTES  (ENC_SMEM_FLOATS * 4)
#define ENC_H2_OFF   0
#define ENC_ENC_OFF  2048

__global__ void __launch_bounds__(256, 3)
enc_kernel(const int* __restrict__ ti, const float* __restrict__ emb,
           const float* __restrict__ w1, const float* __restrict__ b1,
           const float* __restrict__ w2, const float* __restrict__ b2,
           const float* __restrict__ w3, const float* __restrict__ b3,
           const float* __restrict__ cb)
{
    extern __shared__ float s[];
    float* SA  = s + ENC_SA;
    float* X   = SA;
    float* H1  = s + ENC_H1;
    float* WB  = s + ENC_WB;
    float* CB  = s + ENC_CB;
    float* DIST= s + ENC_DIST;
    float* BS  = s + ENC_BS;
    float* H2  = SA + ENC_H2_OFF;
    float* ENC = SA + ENC_ENC_OFF;
    __shared__ int   codes_s[30];
    __shared__ float mind_s[30];

    const int tid = threadIdx.x;
    const int b   = blockIdx.x;

    // zero X and H1 halos; load codebook + w1 + b1
    for (int i = tid; i < 4224; i += 256) { X[i] = 0.f; H1[i] = 0.f; }
    for (int i = tid; i < 640; i += 256) CB[i] = cb[i];
    for (int i = tid; i < 6144; i += 256) WB[i] = w1[i];
    if (tid < 64) BS[tid] = b1[tid];
    __syncthreads();

    // gather: X[e][l+1] = emb[ti[l]*32 + e]
    const int* tirow = ti + b * LL;
    for (int i = tid; i < LL * EE; i += 256) {
        int l = i >> 5, e = i & 31;
        X[e * 132 + l + 1] = emb[tirow[l] * EE + e];
    }
    __syncthreads();

    // conv1: [32][128] pad1 s2 k3 -> H1 [64][64], ReLU.  2o x 8t, 256 threads
    {
        int o0 = (tid & 31) * 2;
        int t0 = (tid >> 5) * 8;
        float acc0[8], acc1[8];
        float bb0 = BS[o0], bb1 = BS[o0 + 1];
        #pragma unroll
        for (int u = 0; u < 8; u++) { acc0[u] = bb0; acc1[u] = bb1; }
        for (int e = 0; e < 32; e++) {
            float xv[17];
            const float* xr = &X[e * 132 + 2 * t0];
            #pragma unroll
            for (int u = 0; u < 17; u++) xv[u] = xr[u];
            const float* wp0 = &WB[(o0 * 32 + e) * 3];
            const float* wp1 = &WB[((o0 + 1) * 32 + e) * 3];
            float a0 = wp0[0], a1 = wp0[1], a2 = wp0[2];
            float c0 = wp1[0], c1 = wp1[1], c2 = wp1[2];
            #pragma unroll
            for (int t = 0; t < 8; t++) {
                float x0 = xv[2*t], x1 = xv[2*t+1], x2 = xv[2*t+2];
                acc0[t] += a0*x0 + a1*x1 + a2*x2;
                acc1[t] += c0*x0 + c1*x1 + c2*x2;
            }
        }
        __syncthreads();   // X no longer needed; SA free for H2 after this phase
        #pragma unroll
        for (int t = 0; t < 8; t++) {
            H1[o0 * 66 + t0 + t + 1]       = fmaxf(acc0[t], 0.f);
            H1[(o0 + 1) * 66 + t0 + t + 1] = fmaxf(acc1[t], 0.f);
        }
    }
    __syncthreads();

    // conv2: H1 [64][64] pad1 s2 k3 -> H2 [64][32], ReLU. 2o x 8t, 128 act threads, e-halves
    {
        bool act = tid < 128;
        int o0 = (tid & 31) * 2;
        int t0 = ((tid >> 5) & 3) * 8;
        float acc0[8], acc1[8];
        #pragma unroll
        for (int half = 0; half < 2; half++) {
            for (int i = tid; i < 6144; i += 256) {
                int o = i / 96;
                WB[i] = w2[i + o * 96 + half * 96];   // [o][e_half 0..31][k]
            }
            if (half == 0 && tid < 64) BS[tid] = b2[tid];
            __syncthreads();
            if (act) {
                if (half == 0) {
                    float bb0 = BS[o0], bb1 = BS[o0 + 1];
                    #pragma unroll
                    for (int u = 0; u < 8; u++) { acc0[u] = bb0; acc1[u] = bb1; }
                }
                for (int e = 0; e < 32; e++) {
                    float xv[17];
                    const float* xr = &H1[(half * 32 + e) * 66 + 2 * t0];
                    #pragma unroll
                    for (int u = 0; u < 17; u++) xv[u] = xr[u];
                    const float* wp0 = &WB[(o0 * 32 + e) * 3];
                    const float* wp1 = &WB[((o0 + 1) * 32 + e) * 3];
                    float a0 = wp0[0], a1 = wp0[1], a2 = wp0[2];
                    float c0 = wp1[0], c1 = wp1[1], c2 = wp1[2];
                    #pragma unroll
                    for (int t = 0; t < 8; t++) {
                        float x0 = xv[2*t], x1 = xv[2*t+1], x2 = xv[2*t+2];
                        acc0[t] += a0*x0 + a1*x1 + a2*x2;
                        acc1[t] += c0*x0 + c1*x1 + c2*x2;
                    }
                }
            }
            __syncthreads();
        }
        if (act) {
            #pragma unroll
            for (int t = 0; t < 8; t++) {
                H2[o0 * 32 + t0 + t]       = fmaxf(acc0[t], 0.f);
                H2[(o0 + 1) * 32 + t0 + t] = fmaxf(acc1[t], 0.f);
            }
        }
    }
    __syncthreads();

    // conv3: H2 [64][32] pad0 s1 k3 -> ENC [30][64] (transposed store). 2o x 5t, 192 act, e-halves
    {
        bool act = tid < 192;
        int o0 = (tid & 31) * 2;
        int t0 = (tid >> 5) * 5;
        float acc0[5], acc1[5];
        #pragma unroll
        for (int half = 0; half < 2; half++) {
            for (int i = tid; i < 6144; i += 256) {
                int o = i / 96;
                WB[i] = w3[i + o * 96 + half * 96];
            }
            if (half == 0 && tid < 64) BS[tid] = b3[tid];
            __syncthreads();
            if (act) {
                if (half == 0) {
                    float bb0 = BS[o0], bb1 = BS[o0 + 1];
                    #pragma unroll
                    for (int u = 0; u < 5; u++) { acc0[u] = bb0; acc1[u] = bb1; }
                }
                for (int e = 0; e < 32; e++) {
                    float xv[7];
                    const float* xr = &H2[(half * 32 + e) * 32 + t0];
                    #pragma unroll
                    for (int u = 0; u < 7; u++) xv[u] = xr[u];
                    const float* wp0 = &WB[(o0 * 32 + e) * 3];
                    const float* wp1 = &WB[((o0 + 1) * 32 + e) * 3];
                    float a0 = wp0[0], a1 = wp0[1], a2 = wp0[2];
                    float c0 = wp1[0], c1 = wp1[1], c2 = wp1[2];
                    #pragma unroll
                    for (int t = 0; t < 5; t++) {
                        acc0[t] += a0*xv[t] + a1*xv[t+1] + a2*xv[t+2];
                        acc1[t] += c0*xv[t] + c1*xv[t+1] + c2*xv[t+2];
                    }
                }
            }
            __syncthreads();
        }
        if (act) {
            #pragma unroll
            for (int t = 0; t < 5; t++) {
                ENC[(t0 + t) * 64 + o0]     = acc0[t];
                ENC[(t0 + t) * 64 + o0 + 1] = acc1[t];
            }
        }
    }
    __syncthreads();

    // VQ distances: 30 rows x 10 codes
    for (int idx = tid; idx < 300; idx += 256) {
        int i = idx / 10, c = idx - i * 10;
        const float* fe = &ENC[i * 64];
        const float* cc = &CB[c * 64];
        float acc = 0.f;
        #pragma unroll 8
        for (int d = 0; d < 64; d++) { float df = fe[d] - cc[d]; acc += df * df; }
        DIST[i * 10 + c] = acc;
    }
    __syncthreads();
    if (tid < 30) {
        float mv = DIST[tid * 10]; int mc = 0;
        #pragma unroll
        for (int c = 1; c < 10; c++) {
            float v = DIST[tid * 10 + c];
            if (v < mv) { mv = v; mc = c; }
        }
        codes_s[tid] = mc;
        mind_s[tid] = mv;
        g_codes[b * 30 + tid] = mc;
    }
    __syncthreads();
    if (tid == 0) {
        float acc = 0.f;
        #pragma unroll
        for (int i = 0; i < 30; i++) acc += mind_s[i];
        g_partial[b] = acc;
    }

    // write ENC rows to scratch (float4 coalesced)
    {
        float4* dst = (float4*)g_enc + (size_t)b * 480;
        const float4* src = (const float4*)ENC;
        for (int i = tid; i < 480; i += 256) dst[i] = src[i];
    }
}

// ---------------- Broadcast fill: features / quantized_st / puzzles ----------------
__global__ void __launch_bounds__(256)
fill_kernel(const float* __restrict__ cb,
            float* __restrict__ out_feat, float* __restrict__ out_qst,
            float* __restrict__ out_puzz)
{
    __shared__ float4 er[16];
    __shared__ float4 cr[16];
    const int blk = blockIdx.x;
    const int b = blk / 30;
    const int i = blk - b * 30;
    const int t = threadIdx.x;

    const int code = __ldg(&g_codes[b * 30 + i]);
    if (t < 16) {
        er[t] = ((const float4*)g_enc)[(size_t)b * 480 + i * 16 + t];
    } else if (t < 32) {
        cr[t - 16] = ((const float4*)cb)[code * 16 + (t - 16)];
    }
    __syncthreads();

    const int q = t & 15;
    float4 ev = er[q];
    float4 cv = cr[q];
    size_t base = (size_t)b * 14400 + (size_t)i * 480;
    float4* f4 = (float4*)out_feat + base;
    float4* q4 = (float4*)out_qst  + base;
    f4[t] = ev;
    q4[t] = cv;
    if (t < 224) {
        f4[t + 256] = ev;
        q4[t + 256] = cv;
    }
    if (t < 30) out_puzz[(size_t)b * 900 + i * 30 + t] = (float)code;
}

// ---------------- Decoder shared layout (floats) ----------------
// REG0 (4608): F [64][36] @0 + G1 [64][36]... actually F=2304 ([64][36]/... see below), G1 @2304;
//              later G3 [32][132] (4224) aliases the whole region
// G2  (4352): [64][68]
// WB  (8192), CB (640), BS (64), OB (128)
#define DEC_REG0 0
#define DEC_F    0
#define DEC_G1   2304
#define DEC_G3   0
#define DEC_G2   4608
#define DEC_WB   8960
#define DEC_CB   17152
#define DEC_BS   17792
#define DEC_OB   17856
#define DEC_SMEM_FLOATS 17984
#define DEC_SMEM_BYTES  (DEC_SMEM_FLOATS * 4)

__global__ void __launch_bounds__(256, 3)
dec_kernel(const float* __restrict__ cb,
           const float* __restrict__ dw1, const float* __restrict__ db1,
           const float* __restrict__ dw2, const float* __restrict__ db2,
           const float* __restrict__ dw3, const float* __restrict__ db3,
           const float* __restrict__ ow,  const float* __restrict__ ob,
           float* __restrict__ out_logits)
{
    extern __shared__ float s[];
    float* F  = s + DEC_F;
    float* G1 = s + DEC_G1;
    float* G2 = s + DEC_G2;
    float* G3 = s + DEC_G3;
    float* WB = s + DEC_WB;
    float* CB = s + DEC_CB;
    float* BS = s + DEC_BS;
    float* OB = s + DEC_OB;
    __shared__ int codes_s[30];

    const int tid = threadIdx.x;
    const int b   = blockIdx.x;

    // zero F+G1 region and G2 (halos)
    for (int i = tid; i < 4608; i += 256) s[DEC_REG0 + i] = 0.f;
    for (int i = tid; i < 4352; i += 256) G2[i] = 0.f;
    for (int i = tid; i < 640; i += 256) CB[i] = cb[i];
    if (tid < 30) codes_s[tid] = g_codes[b * 30 + tid];
    for (int i = tid; i < 6144; i += 256) WB[i] = dw1[i];
    if (tid < 64) BS[tid] = db1[tid];
    __syncthreads();

    // F[d][i+2] = codebook[code[i]][d]
    for (int idx = tid; idx < 64 * 30; idx += 256) {
        int d = idx / 30, i = idx - d * 30;
        F[d * 36 + i + 2] = CB[codes_s[i] * 64 + d];
    }
    __syncthreads();

    // convT1: [64][30] s1 p0 k3 -> G1 [64][32], ReLU. 2o x 8t, 128 act, c-halves
    {
        int o0 = (tid & 31) * 2;
        int t0 = ((tid >> 5) & 3) * 8;
        bool act1 = tid < 128;
        float ac0[8], ac1[8];
        if (act1) {
            float bb0 = BS[o0], bb1 = BS[o0 + 1];
            #pragma unroll
            for (int u = 0; u < 8; u++) { ac0[u] = bb0; ac1[u] = bb1; }
            for (int c = 0; c < 32; c++) {
                float xv[10];
                const float* xr = &F[c * 36 + t0];
                #pragma unroll
                for (int u = 0; u < 10; u++) xv[u] = xr[u];
                const float* wp0 = &WB[(c * 64 + o0) * 3];
                const float* wp1 = &WB[(c * 64 + o0 + 1) * 3];
                float a0 = wp0[0], a1 = wp0[1], a2 = wp0[2];
                float c0 = wp1[0], c1 = wp1[1], c2 = wp1[2];
                #pragma unroll
                for (int t = 0; t < 8; t++) {
                    ac0[t] += a0*xv[t+2] + a1*xv[t+1] + a2*xv[t];
                    ac1[t] += c0*xv[t+2] + c1*xv[t+1] + c2*xv[t];
                }
            }
        }
        __syncthreads();
        for (int i = tid; i < 6144; i += 256) WB[i] = dw1[6144 + i];
        __syncthreads();
        if (act1) {
            for (int c = 0; c < 32; c++) {
                float xv[10];
                const float* xr = &F[(c + 32) * 36 + t0];
                #pragma unroll
                for (int u = 0; u < 10; u++) xv[u] = xr[u];
                const float* wp0 = &WB[(c * 64 + o0) * 3];
                const float* wp1 = &WB[(c * 64 + o0 + 1) * 3];
                float a0 = wp0[0], a1 = wp0[1], a2 = wp0[2];
                float c0 = wp1[0], c1 = wp1[1], c2 = wp1[2];
                #pragma unroll
                for (int t = 0; t < 8; t++) {
                    ac0[t] += a0*xv[t+2] + a1*xv[t+1] + a2*xv[t];
                    ac1[t] += c0*xv[t+2] + c1*xv[t+1] + c2*xv[t];
                }
            }
            #pragma unroll
            for (int t = 0; t < 8; t++) {
                G1[o0 * 36 + t0 + t + 1]       = fmaxf(ac0[t], 0.f);
                G1[(o0 + 1) * 36 + t0 + t + 1] = fmaxf(ac1[t], 0.f);
            }
        }
    }
    __syncthreads();

    // convT2: G1 [64][32] s2 p1 k4 -> G2 [64][64], ReLU. 2o x 8t, 256 threads, c-halves
    {
        int oo = (tid & 31) * 2;
        int tt0 = (tid >> 5) * 8;
        float b20[8], b21[8];
        for (int i = tid; i < 8192; i += 256) WB[i] = dw2[i];
        if (tid < 64) BS[tid] = db2[tid];
        __syncthreads();
        {
            float bb0 = BS[oo], bb1 = BS[oo + 1];
            #pragma unroll
            for (int u = 0; u < 8; u++) { b20[u] = bb0; b21[u] = bb1; }
        }
        for (int half = 0; half < 2; half++) {
            if (half == 1) {
                __syncthreads();
                for (int i = tid; i < 8192; i += 256) WB[i] = dw2[8192 + i];
                __syncthreads();
            }
            int cbase = half * 32;
            for (int c = 0; c < 32; c++) {
                float xv[6];
                const float* xr = &G1[(c + cbase) * 36 + (tt0 >> 1)];
                #pragma unroll
                for (int u = 0; u < 6; u++) xv[u] = xr[u];
                const float* wp0 = &WB[(c * 64 + oo) * 4];
                const float* wp1 = &WB[(c * 64 + oo + 1) * 4];
                float a0 = wp0[0], a1 = wp0[1], a2 = wp0[2], a3 = wp0[3];
                float c0 = wp1[0], c1 = wp1[1], c2 = wp1[2], c3 = wp1[3];
                #pragma unroll
                for (int t = 0; t < 8; t++) {
                    int u1 = ((t + 1) >> 1) + 1;
                    float xh = xv[u1], xl = xv[u1 - 1];
                    if (t & 1) {
                        b20[t] += a0 * xh + a2 * xl;
                        b21[t] += c0 * xh + c2 * xl;
                    } else {
                        b20[t] += a1 * xh + a3 * xl;
                        b21[t] += c1 * xh + c3 * xl;
                    }
                }
            }
        }
        #pragma unroll
        for (int t = 0; t < 8; t++) {
            G2[oo * 68 + tt0 + t + 1]       = fmaxf(b20[t], 0.f);
            G2[(oo + 1) * 68 + tt0 + t + 1] = fmaxf(b21[t], 0.f);
        }
    }
    __syncthreads();

    // convT3: G2 [64][64] s2 p1 k4 -> G3 [32][128] (aliases F/G1, now dead). 2o x 8t, 256 threads
    {
        int oo = (tid & 15) * 2;
        int tt0 = (tid >> 4) * 8;
        float b30[8], b31[8];
        for (int i = tid; i < 8192; i += 256) WB[i] = dw3[i];
        if (tid < 32) BS[tid] = db3[tid];
        __syncthreads();
        {
            float bb0 = BS[oo], bb1 = BS[oo + 1];
            #pragma unroll
            for (int u = 0; u < 8; u++) { b30[u] = bb0; b31[u] = bb1; }
        }
        for (int c = 0; c < 64; c++) {
            float xv[6];
            const float* xr = &G2[c * 68 + (tt0 >> 1)];
            #pragma unroll
            for (int u = 0; u < 6; u++) xv[u] = xr[u];
            const float* wp0 = &WB[(c * 32 + oo) * 4];
            const float* wp1 = &WB[(c * 32 + oo + 1) * 4];
            float a0 = wp0[0], a1 = wp0[1], a2 = wp0[2], a3 = wp0[3];
            float c0 = wp1[0], c1 = wp1[1], c2 = wp1[2], c3 = wp1[3];
            #pragma unroll
            for (int t = 0; t < 8; t++) {
                int u1 = ((t + 1) >> 1) + 1;
                float xh = xv[u1], xl = xv[u1 - 1];
                if (t & 1) {
                    b30[t] += a0 * xh + a2 * xl;
                    b31[t] += c0 * xh + c2 * xl;
                } else {
                    b30[t] += a1 * xh + a3 * xl;
                    b31[t] += c1 * xh + c3 * xl;
                }
            }
        }
        __syncthreads();   // G1 reads done before aliased G3 writes
        #pragma unroll
        for (int t = 0; t < 8; t++) {
            G3[oo * 132 + tt0 + t]       = b30[t];
            G3[(oo + 1) * 132 + tt0 + t] = b31[t];
        }
    }
    __syncthreads();

    // final GEMM: logits[l][v] = sum_e G3[e][l] * ow[v*32+e] + ob[v].  4v x 16l per thread
    {
        for (int i = tid; i < 4096; i += 256) WB[i] = ow[i];
        if (tid < 128) OB[tid] = ob[tid];
        __syncthreads();
        int v0 = (tid & 31) * 4;
        int l0 = (tid >> 5) * 16;
        float ga[4][16];
        #pragma unroll
        for (int j = 0; j < 4; j++) {
            float bj = OB[v0 + j];
            #pragma unroll
            for (int u = 0; u < 16; u++) ga[j][u] = bj;
        }
        for (int e = 0; e < 32; e++) {
            float xv[16];
            const float* xr = &G3[e * 132 + l0];
            #pragma unroll
            for (int u = 0; u < 16; u++) xv[u] = xr[u];
            float w0 = WB[(v0 + 0) * 32 + e];
            float w1 = WB[(v0 + 1) * 32 + e];
            float w2 = WB[(v0 + 2) * 32 + e];
            float w3 = WB[(v0 + 3) * 32 + e];
            #pragma unroll
            for (int u = 0; u < 16; u++) {
                float x = xv[u];
                ga[0][u] += w0 * x;
                ga[1][u] += w1 * x;
                ga[2][u] += w2 * x;
                ga[3][u] += w3 * x;
            }
        }
        float* outp = out_logits + ((size_t)b * 128 + l0) * 128 + v0;
        #pragma unroll
        for (int u = 0; u < 16; u++) {
            float4 vv = make_float4(ga[0][u], ga[1][u], ga[2][u], ga[3][u]);
            *(float4*)(outp + (size_t)u * 128) = vv;
        }
    }
}

// Deterministic loss reduce
__global__ void loss_kernel(float* __restrict__ out_loss)
{
    __shared__ float sm[256];
    float a = 0.f;
    for (int i = threadIdx.x; i < BB; i += 256) a += g_partial[i];
    sm[threadIdx.x] = a;
    __syncthreads();
    for (int sft = 128; sft > 0; sft >>= 1) {
        if (threadIdx.x < sft) sm[threadIdx.x] += sm[threadIdx.x + sft];
        __syncthreads();
    }
    if (threadIdx.x == 0)
        out_loss[0] = sm[0] * (1.25f / (2048.f * 30.f * 64.f));
}

extern "C" void kernel_launch(void* const* d_in, const int* in_sizes, int n_in,
                              void* d_out, int out_size)
{
    const int*   ti     = (const int*)  d_in[0];
    const float* emb    = (const float*)d_in[1];
    const float* enc_w1 = (const float*)d_in[2];
    const float* enc_b1 = (const float*)d_in[3];
    const float* enc_w2 = (const float*)d_in[4];
    const float* enc_b2 = (const float*)d_in[5];
    const float* enc_w3 = (const float*)d_in[6];
    const float* enc_b3 = (const float*)d_in[7];
    const float* cb     = (const float*)d_in[8];
    const float* dec_w1 = (const float*)d_in[9];
    const float* dec_b1 = (const float*)d_in[10];
    const float* dec_w2 = (const float*)d_in[11];
    const float* dec_b2 = (const float*)d_in[12];
    const float* dec_w3 = (const float*)d_in[13];
    const float* dec_b3 = (const float*)d_in[14];
    const float* out_w  = (const float*)d_in[15];
    const float* out_b  = (const float*)d_in[16];

    float* out        = (float*)d_out;
    float* out_logits = out;
    float* out_puzz   = out + OFF_PUZZ;
    float* out_feat   = out + OFF_FEAT;
    float* out_qst    = out + OFF_QST;
    float* out_loss   = out + OFF_LOSS;

    cudaFuncSetAttribute(enc_kernel, cudaFuncAttributeMaxDynamicSharedMemorySize, ENC_SMEM_BYTES);
    cudaFuncSetAttribute(dec_kernel, cudaFuncAttributeMaxDynamicSharedMemorySize, DEC_SMEM_BYTES);

    enc_kernel<<<BB, 256, ENC_SMEM_BYTES>>>(ti, emb, enc_w1, enc_b1, enc_w2, enc_b2,
                                            enc_w3, enc_b3, cb);
    fill_kernel<<<BB * 30, 256>>>(cb, out_feat, out_qst, out_puzz);
    dec_kernel<<<BB, 256, DEC_SMEM_BYTES>>>(cb, dec_w1, dec_b1, dec_w2, dec_b2,
                                            dec_w3, dec_b3, out_w, out_b, out_logits);
    loss_kernel<<<1, 256>>>(out_loss);
}

// round 3
// speedup vs baseline: 2.6160x; 2.6160x over previous
#include <cuda_runtime.h>
#include <cstdint>

// Problem constants
#define BB   2048
#define LL   128
#define VV   128
#define EE   32
#define DD   64
#define NCB  10

// Output layout (concatenated, float32)
#define OFF_PUZZ  33554432
#define OFF_FEAT  35397632
#define OFF_QST   153362432
#define OFF_LOSS  271327232

// Scratch
__device__ int   g_codes[BB * 30];
__device__ float g_partial[BB];
__device__ float g_enc[BB * 30 * DD];

// ---------------- Encoder shared layout (floats) ----------------
// SA  (4224): X [32][132] during gather/conv1; then H2 [64][32] @0 + ENC [30][64] @2048
// H1  (4224): [64][66]
// WT  (6336): transposed weights [(e*3+k)][66 pad, o fastest]
// CB (640), DIST (304), BS (64)
#define ENC_SA   0
#define ENC_H1   4224
#define ENC_WT   8448
#define ENC_CB   14784
#define ENC_DIST 15424
#define ENC_BS   15728
#define ENC_SMEM_FLOATS 15792
#define ENC_SMEM_BYTES  (ENC_SMEM_FLOATS * 4)
#define ENC_H2_OFF   0
#define ENC_ENC_OFF  2048

__global__ void __launch_bounds__(256, 3)
enc_kernel(const int* __restrict__ ti, const float* __restrict__ emb,
           const float* __restrict__ w1, const float* __restrict__ b1,
           const float* __restrict__ w2, const float* __restrict__ b2,
           const float* __restrict__ w3, const float* __restrict__ b3,
           const float* __restrict__ cb)
{
    extern __shared__ float s[];
    float* SA  = s + ENC_SA;
    float* X   = SA;
    float* H1  = s + ENC_H1;
    float* WT  = s + ENC_WT;
    float* CB  = s + ENC_CB;
    float* DIST= s + ENC_DIST;
    float* BS  = s + ENC_BS;
    float* H2  = SA + ENC_H2_OFF;
    float* ENC = SA + ENC_ENC_OFF;
    __shared__ int   codes_s[30];
    __shared__ float mind_s[30];

    const int tid = threadIdx.x;
    const int b   = blockIdx.x;

    // zero halos; load codebook; stage w1 transposed: WT[(e*3+k)*66 + o] = w1[o*96 + e*3+k]
    for (int i = tid; i < 4224; i += 256) { X[i] = 0.f; H1[i] = 0.f; }
    for (int i = tid; i < 640; i += 256) CB[i] = cb[i];
    for (int i = tid; i < 6144; i += 256) {
        int o = i / 96, r = i - o * 96;
        WT[r * 66 + o] = w1[i];
    }
    if (tid < 64) BS[tid] = b1[tid];
    __syncthreads();

    // gather: X[e][l+1] = emb[ti[l]*32 + e]
    const int* tirow = ti + b * LL;
    for (int i = tid; i < LL * EE; i += 256) {
        int l = i >> 5, e = i & 31;
        X[e * 132 + l + 1] = emb[tirow[l] * EE + e];
    }
    __syncthreads();

    // conv1: X [32][128] pad1 s2 k3 -> H1 [64][64], ReLU.  2o x 8t, 256 threads
    {
        const int o0 = (tid & 31) * 2;
        const int t0 = (tid >> 5) * 8;
        float acc0[8], acc1[8];
        float bb0 = BS[o0], bb1 = BS[o0 + 1];
        #pragma unroll
        for (int u = 0; u < 8; u++) { acc0[u] = bb0; acc1[u] = bb1; }
        for (int e = 0; e < 32; e++) {
            float xv[17];
            const float* xr = &X[e * 132 + 2 * t0];
            #pragma unroll
            for (int u = 0; u < 17; u++) xv[u] = xr[u];
            #pragma unroll
            for (int k = 0; k < 3; k++) {
                float2 w = *(const float2*)&WT[(e * 3 + k) * 66 + o0];
                #pragma unroll
                for (int t = 0; t < 8; t++) {
                    float x = xv[2 * t + k];
                    acc0[t] += w.x * x;
                    acc1[t] += w.y * x;
                }
            }
        }
        #pragma unroll
        for (int t = 0; t < 8; t++) {
            H1[o0 * 66 + t0 + t + 1]       = fmaxf(acc0[t], 0.f);
            H1[(o0 + 1) * 66 + t0 + t + 1] = fmaxf(acc1[t], 0.f);
        }
    }
    __syncthreads();

    // conv2: H1 [64][64] pad1 s2 k3 -> H2 [64][32], ReLU.  2o x 4t, 256 threads, e-halves
    {
        const int o0 = (tid & 31) * 2;
        const int t0 = (tid >> 5) * 4;
        float acc0[4], acc1[4];
        #pragma unroll
        for (int half = 0; half < 2; half++) {
            // stage WT[(e*3+k)*66+o] = w2[o*192 + 96*half + (e*3+k)]
            for (int i = tid; i < 6144; i += 256) {
                int o = i / 96, r = i - o * 96;
                WT[r * 66 + o] = w2[o * 192 + 96 * half + r];
            }
            if (half == 0 && tid < 64) BS[tid] = b2[tid];
            __syncthreads();
            if (half == 0) {
                float bb0 = BS[o0], bb1 = BS[o0 + 1];
                #pragma unroll
                for (int u = 0; u < 4; u++) { acc0[u] = bb0; acc1[u] = bb1; }
            }
            for (int e = 0; e < 32; e++) {
                float xv[9];
                const float* xr = &H1[(half * 32 + e) * 66 + 2 * t0];
                #pragma unroll
                for (int u = 0; u < 9; u++) xv[u] = xr[u];
                #pragma unroll
                for (int k = 0; k < 3; k++) {
                    float2 w = *(const float2*)&WT[(e * 3 + k) * 66 + o0];
                    #pragma unroll
                    for (int t = 0; t < 4; t++) {
                        float x = xv[2 * t + k];
                        acc0[t] += w.x * x;
                        acc1[t] += w.y * x;
                    }
                }
            }
            __syncthreads();
        }
        #pragma unroll
        for (int t = 0; t < 4; t++) {
            H2[o0 * 32 + t0 + t]       = fmaxf(acc0[t], 0.f);
            H2[(o0 + 1) * 32 + t0 + t] = fmaxf(acc1[t], 0.f);
        }
    }
    __syncthreads();

    // conv3: H2 [64][32] pad0 s1 k3 -> ENC [30][64] transposed.  2o x 5t, 192 act, e-halves
    {
        const bool act = tid < 192;
        const int o0 = (tid & 31) * 2;
        const int t0 = (tid >> 5) * 5;
        float acc0[5], acc1[5];
        #pragma unroll
        for (int half = 0; half < 2; half++) {
            for (int i = tid; i < 6144; i += 256) {
                int o = i / 96, r = i - o * 96;
                WT[r * 66 + o] = w3[o * 192 + 96 * half + r];
            }
            if (half == 0 && tid < 64) BS[tid] = b3[tid];
            __syncthreads();
            if (act) {
                if (half == 0) {
                    float bb0 = BS[o0], bb1 = BS[o0 + 1];
                    #pragma unroll
                    for (int u = 0; u < 5; u++) { acc0[u] = bb0; acc1[u] = bb1; }
                }
                for (int e = 0; e < 32; e++) {
                    float xv[7];
                    const float* xr = &H2[(half * 32 + e) * 32 + t0];
                    #pragma unroll
                    for (int u = 0; u < 7; u++) xv[u] = xr[u];
                    #pragma unroll
                    for (int k = 0; k < 3; k++) {
                        float2 w = *(const float2*)&WT[(e * 3 + k) * 66 + o0];
                        #pragma unroll
                        for (int t = 0; t < 5; t++) {
                            float x = xv[t + k];
                            acc0[t] += w.x * x;
                            acc1[t] += w.y * x;
                        }
                    }
                }
            }
            __syncthreads();
        }
        if (act) {
            #pragma unroll
            for (int t = 0; t < 5; t++) {
                ENC[(t0 + t) * 64 + o0]     = acc0[t];
                ENC[(t0 + t) * 64 + o0 + 1] = acc1[t];
            }
        }
    }
    __syncthreads();

    // VQ distances
    for (int idx = tid; idx < 300; idx += 256) {
        int i = idx / 10, c = idx - i * 10;
        const float* fe = &ENC[i * 64];
        const float* cc = &CB[c * 64];
        float acc = 0.f;
        #pragma unroll 8
        for (int d = 0; d < 64; d++) { float df = fe[d] - cc[d]; acc += df * df; }
        DIST[i * 10 + c] = acc;
    }
    __syncthreads();
    if (tid < 30) {
        float mv = DIST[tid * 10]; int mc = 0;
        #pragma unroll
        for (int c = 1; c < 10; c++) {
            float v = DIST[tid * 10 + c];
            if (v < mv) { mv = v; mc = c; }
        }
        codes_s[tid] = mc;
        mind_s[tid] = mv;
        g_codes[b * 30 + tid] = mc;
    }
    __syncthreads();
    if (tid == 0) {
        float acc = 0.f;
        #pragma unroll
        for (int i = 0; i < 30; i++) acc += mind_s[i];
        g_partial[b] = acc;
    }

    // write ENC rows to scratch
    {
        float4* dst = (float4*)g_enc + (size_t)b * 480;
        const float4* src = (const float4*)ENC;
        for (int i = tid; i < 480; i += 256) dst[i] = src[i];
    }
}

// ---------------- Broadcast fill ----------------
__global__ void __launch_bounds__(256)
fill_kernel(const float* __restrict__ cb,
            float* __restrict__ out_feat, float* __restrict__ out_qst,
            float* __restrict__ out_puzz)
{
    __shared__ float4 er[16];
    __shared__ float4 cr[16];
    const int blk = blockIdx.x;
    const int b = blk / 30;
    const int i = blk - b * 30;
    const int t = threadIdx.x;

    const int code = __ldg(&g_codes[b * 30 + i]);
    if (t < 16) {
        er[t] = ((const float4*)g_enc)[(size_t)b * 480 + i * 16 + t];
    } else if (t < 32) {
        cr[t - 16] = ((const float4*)cb)[code * 16 + (t - 16)];
    }
    __syncthreads();

    const int q = t & 15;
    float4 ev = er[q];
    float4 cv = cr[q];
    size_t base = (size_t)b * 14400 + (size_t)i * 480;
    float4* f4 = (float4*)out_feat + base;
    float4* q4 = (float4*)out_qst  + base;
    f4[t] = ev;
    q4[t] = cv;
    if (t < 224) {
        f4[t + 256] = ev;
        q4[t + 256] = cv;
    }
    if (t < 30) out_puzz[(size_t)b * 900 + i * 30 + t] = (float)code;
}

// ---------------- Decoder shared layout (floats) ----------------
// REG0 (4608): F [64][36] @0 + G1 [64][36] @2304; later G3 [32][132] aliases it
// G2 (4352): [64][68];  WT (8704 max);  CB (640), BS (64), OB (128)
#define DEC_REG0 0
#define DEC_F    0
#define DEC_G1   2304
#define DEC_G3   0
#define DEC_G2   4608
#define DEC_WT   8960
#define DEC_CB   17664
#define DEC_BS   18304
#define DEC_OB   18368
#define DEC_SMEM_FLOATS 18496
#define DEC_SMEM_BYTES  (DEC_SMEM_FLOATS * 4)

__global__ void __launch_bounds__(256, 3)
dec_kernel(const float* __restrict__ cb,
           const float* __restrict__ dw1, const float* __restrict__ db1,
           const float* __restrict__ dw2, const float* __restrict__ db2,
           const float* __restrict__ dw3, const float* __restrict__ db3,
           const float* __restrict__ ow,  const float* __restrict__ ob,
           float* __restrict__ out_logits)
{
    extern __shared__ float s[];
    float* F  = s + DEC_F;
    float* G1 = s + DEC_G1;
    float* G2 = s + DEC_G2;
    float* G3 = s + DEC_G3;
    float* WT = s + DEC_WT;
    float* CB = s + DEC_CB;
    float* BS = s + DEC_BS;
    float* OB = s + DEC_OB;
    __shared__ int codes_s[30];

    const int tid = threadIdx.x;
    const int b   = blockIdx.x;

    for (int i = tid; i < 4608; i += 256) s[DEC_REG0 + i] = 0.f;
    for (int i = tid; i < 4352; i += 256) G2[i] = 0.f;
    for (int i = tid; i < 640; i += 256) CB[i] = cb[i];
    if (tid < 30) codes_s[tid] = g_codes[b * 30 + tid];
    if (tid < 64) BS[tid] = db1[tid];
    __syncthreads();

    // F[d][i+2] = codebook[code[i]][d]
    for (int idx = tid; idx < 64 * 30; idx += 256) {
        int d = idx / 30, i = idx - d * 30;
        F[d * 36 + i + 2] = CB[codes_s[i] * 64 + d];
    }

    // convT1: F [64][30] s1 p0 k3 -> G1 [64][32], ReLU.  2o x 4t, 256 threads, c-halves
    {
        const int o0 = (tid & 31) * 2;
        const int t0 = (tid >> 5) * 4;
        float ac0[4], ac1[4];
        {
            float bb0 = BS[o0], bb1 = BS[o0 + 1];
            #pragma unroll
            for (int u = 0; u < 4; u++) { ac0[u] = bb0; ac1[u] = bb1; }
        }
        #pragma unroll
        for (int half = 0; half < 2; half++) {
            __syncthreads();
            // stage WT[(cl*3+k)*66+o] = dw1[(cl+32h)*192 + o*3 + k]
            for (int i = tid; i < 6144; i += 256) {
                int o = i & 63, q = i >> 6;
                int cl = q / 3, k = q - cl * 3;
                WT[q * 66 + o] = dw1[(cl + 32 * half) * 192 + o * 3 + k];
            }
            __syncthreads();
            for (int cl = 0; cl < 32; cl++) {
                float xv[6];
                const float* xr = &F[(half * 32 + cl) * 36 + t0];
                #pragma unroll
                for (int u = 0; u < 6; u++) xv[u] = xr[u];
                #pragma unroll
                for (int k = 0; k < 3; k++) {
                    float2 w = *(const float2*)&WT[(cl * 3 + k) * 66 + o0];
                    #pragma unroll
                    for (int t = 0; t < 4; t++) {
                        float x = xv[t + 2 - k];
                        ac0[t] += w.x * x;
                        ac1[t] += w.y * x;
                    }
                }
            }
        }
        __syncthreads();
        #pragma unroll
        for (int t = 0; t < 4; t++) {
            G1[o0 * 36 + t0 + t + 1]       = fmaxf(ac0[t], 0.f);
            G1[(o0 + 1) * 36 + t0 + t + 1] = fmaxf(ac1[t], 0.f);
        }
    }
    __syncthreads();

    // convT2: G1 [64][32] s2 p1 k4 -> G2 [64][64], ReLU.  2o x 8t, c-halves
    {
        const int oo = (tid & 31) * 2;
        const int tt0 = (tid >> 5) * 8;
        float b20[8], b21[8];
        if (tid < 64) BS[tid] = db2[tid];
        __syncthreads();
        {
            float bb0 = BS[oo], bb1 = BS[oo + 1];
            #pragma unroll
            for (int u = 0; u < 8; u++) { b20[u] = bb0; b21[u] = bb1; }
        }
        #pragma unroll
        for (int half = 0; half < 2; half++) {
            if (half) __syncthreads();
            // stage WT[(cl*4+k)*66+o] = dw2[(cl+32h)*256 + o*4 + k]
            for (int i = tid; i < 8192; i += 256) {
                int o = i & 63, q = i >> 6;
                int cl = q >> 2, k = q & 3;
                WT[q * 66 + o] = dw2[(cl + 32 * half) * 256 + o * 4 + k];
            }
            __syncthreads();
            for (int cl = 0; cl < 32; cl++) {
                float xv[6];
                const float* xr = &G1[(half * 32 + cl) * 36 + (tt0 >> 1)];
                #pragma unroll
                for (int u = 0; u < 6; u++) xv[u] = xr[u];
                float2 w0 = *(const float2*)&WT[(cl * 4 + 0) * 66 + oo];
                float2 w1 = *(const float2*)&WT[(cl * 4 + 1) * 66 + oo];
                float2 w2 = *(const float2*)&WT[(cl * 4 + 2) * 66 + oo];
                float2 w3 = *(const float2*)&WT[(cl * 4 + 3) * 66 + oo];
                #pragma unroll
                for (int t = 0; t < 8; t++) {
                    int u1 = ((t + 1) >> 1) + 1;
                    float xh = xv[u1], xl = xv[u1 - 1];
                    if (t & 1) {
                        b20[t] += w0.x * xh + w2.x * xl;
                        b21[t] += w0.y * xh + w2.y * xl;
                    } else {
                        b20[t] += w1.x * xh + w3.x * xl;
                        b21[t] += w1.y * xh + w3.y * xl;
                    }
                }
            }
        }
        #pragma unroll
        for (int t = 0; t < 8; t++) {
            G2[oo * 68 + tt0 + t + 1]       = fmaxf(b20[t], 0.f);
            G2[(oo + 1) * 68 + tt0 + t + 1] = fmaxf(b21[t], 0.f);
        }
    }
    __syncthreads();

    // convT3: G2 [64][64] s2 p1 k4 -> G3 [32][128] (aliases F/G1).  2o x 8t
    {
        const int oo = (tid & 15) * 2;
        const int tt0 = (tid >> 4) * 8;
        float b30[8], b31[8];
        // stage WT[(c*4+k)*34 + o] = dw3[c*128 + o*4 + k]
        for (int i = tid; i < 8192; i += 256) {
            int o = i & 31, q = i >> 5;
            int c = q >> 2, k = q & 3;
            WT[q * 34 + o] = dw3[c * 128 + o * 4 + k];
        }
        if (tid < 32) BS[tid] = db3[tid];
        __syncthreads();
        {
            float bb0 = BS[oo], bb1 = BS[oo + 1];
            #pragma unroll
            for (int u = 0; u < 8; u++) { b30[u] = bb0; b31[u] = bb1; }
        }
        for (int c = 0; c < 64; c++) {
            float xv[6];
            const float* xr = &G2[c * 68 + (tt0 >> 1)];
            #pragma unroll
            for (int u = 0; u < 6; u++) xv[u] = xr[u];
            float2 w0 = *(const float2*)&WT[(c * 4 + 0) * 34 + oo];
            float2 w1 = *(const float2*)&WT[(c * 4 + 1) * 34 + oo];
            float2 w2 = *(const float2*)&WT[(c * 4 + 2) * 34 + oo];
            float2 w3 = *(const float2*)&WT[(c * 4 + 3) * 34 + oo];
            #pragma unroll
            for (int t = 0; t < 8; t++) {
                int u1 = ((t + 1) >> 1) + 1;
                float xh = xv[u1], xl = xv[u1 - 1];
                if (t & 1) {
                    b30[t] += w0.x * xh + w2.x * xl;
                    b31[t] += w0.y * xh + w2.y * xl;
                } else {
                    b30[t] += w1.x * xh + w3.x * xl;
                    b31[t] += w1.y * xh + w3.y * xl;
                }
            }
        }
        __syncthreads();   // all G1/F reads done before aliased G3 writes
        #pragma unroll
        for (int t = 0; t < 8; t++) {
            G3[oo * 132 + tt0 + t]       = b30[t];
            G3[(oo + 1) * 132 + tt0 + t] = b31[t];
        }
    }
    __syncthreads();

    // final GEMM: logits[l][v] = sum_e G3[e][l] * ow[v*32+e] + ob[v].  4v x 16l per thread
    {
        // stage OWT[e*132 + v] = ow[v*32+e]
        for (int i = tid; i < 4096; i += 256) {
            int v = i >> 5, e = i & 31;
            WT[e * 132 + v] = ow[i];
        }
        if (tid < 128) OB[tid] = ob[tid];
        __syncthreads();
        const int v0 = (tid & 31) * 4;
        const int l0 = (tid >> 5) * 16;
        float ga[4][16];
        #pragma unroll
        for (int j = 0; j < 4; j++) {
            float bj = OB[v0 + j];
            #pragma unroll
            for (int u = 0; u < 16; u++) ga[j][u] = bj;
        }
        for (int e = 0; e < 32; e++) {
            float xv[16];
            const float* xr = &G3[e * 132 + l0];
            #pragma unroll
            for (int u = 0; u < 16; u++) xv[u] = xr[u];
            float4 w = *(const float4*)&WT[e * 132 + v0];
            #pragma unroll
            for (int u = 0; u < 16; u++) {
                float x = xv[u];
                ga[0][u] += w.x * x;
                ga[1][u] += w.y * x;
                ga[2][u] += w.z * x;
                ga[3][u] += w.w * x;
            }
        }
        float* outp = out_logits + ((size_t)b * 128 + l0) * 128 + v0;
        #pragma unroll
        for (int u = 0; u < 16; u++) {
            float4 vv = make_float4(ga[0][u], ga[1][u], ga[2][u], ga[3][u]);
            *(float4*)(outp + (size_t)u * 128) = vv;
        }
    }
}

// Deterministic loss reduce
__global__ void loss_kernel(float* __restrict__ out_loss)
{
    __shared__ float sm[256];
    float a = 0.f;
    for (int i = threadIdx.x; i < BB; i += 256) a += g_partial[i];
    sm[threadIdx.x] = a;
    __syncthreads();
    for (int sft = 128; sft > 0; sft >>= 1) {
        if (threadIdx.x < sft) sm[threadIdx.x] += sm[threadIdx.x + sft];
        __syncthreads();
    }
    if (threadIdx.x == 0)
        out_loss[0] = sm[0] * (1.25f / (2048.f * 30.f * 64.f));
}

extern "C" void kernel_launch(void* const* d_in, const int* in_sizes, int n_in,
                              void* d_out, int out_size)
{
    const int*   ti     = (const int*)  d_in[0];
    const float* emb    = (const float*)d_in[1];
    const float* enc_w1 = (const float*)d_in[2];
    const float* enc_b1 = (const float*)d_in[3];
    const float* enc_w2 = (const float*)d_in[4];
    const float* enc_b2 = (const float*)d_in[5];
    const float* enc_w3 = (const float*)d_in[6];
    const float* enc_b3 = (const float*)d_in[7];
    const float* cb     = (const float*)d_in[8];
    const float* dec_w1 = (const float*)d_in[9];
    const float* dec_b1 = (const float*)d_in[10];
    const float* dec_w2 = (const float*)d_in[11];
    const float* dec_b2 = (const float*)d_in[12];
    const float* dec_w3 = (const float*)d_in[13];
    const float* dec_b3 = (const float*)d_in[14];
    const float* out_w  = (const float*)d_in[15];
    const float* out_b  = (const float*)d_in[16];

    float* out        = (float*)d_out;
    float* out_logits = out;
    float* out_puzz   = out + OFF_PUZZ;
    float* out_feat   = out + OFF_FEAT;
    float* out_qst    = out + OFF_QST;
    float* out_loss   = out + OFF_LOSS;

    cudaFuncSetAttribute(enc_kernel, cudaFuncAttributeMaxDynamicSharedMemorySize, ENC_SMEM_BYTES);
    cudaFuncSetAttribute(dec_kernel, cudaFuncAttributeMaxDynamicSharedMemorySize, DEC_SMEM_BYTES);

    enc_kernel<<<BB, 256, ENC_SMEM_BYTES>>>(ti, emb, enc_w1, enc_b1, enc_w2, enc_b2,
                                            enc_w3, enc_b3, cb);
    fill_kernel<<<BB * 30, 256>>>(cb, out_feat, out_qst, out_puzz);
    dec_kernel<<<BB, 256, DEC_SMEM_BYTES>>>(cb, dec_w1, dec_b1, dec_w2, dec_b2,
                                            dec_w3, dec_b3, out_w, out_b, out_logits);
    loss_kernel<<<1, 256>>>(out_loss);
}

// round 4
// speedup vs baseline: 2.8350x; 1.0837x over previous
#include <cuda_runtime.h>
#include <cstdint>

// Problem constants
#define BB   2048
#define LL   128
#define VV   128
#define EE   32
#define DD   64
#define NCB  10

// Output layout (concatenated, float32)
#define OFF_PUZZ  33554432
#define OFF_FEAT  35397632
#define OFF_QST   153362432
#define OFF_LOSS  271327232

// Scratch
__device__ int   g_codes[BB * 30];
__device__ float g_partial[BB];

// ---------------- Encoder shared layout (floats) ----------------
// SA  (4224): X [32][132] during gather/conv1; then H2 [64][32] @0 + ENC [30][64] @2048
// H1  (4224): [64][66]
// WT  (6336): transposed weights [(e*3+k)][66 pad, o fastest]
// CB (640), DIST (304), BS (64)
#define ENC_SA   0
#define ENC_H1   4224
#define ENC_WT   8448
#define ENC_CB   14784
#define ENC_DIST 15424
#define ENC_BS   15728
#define ENC_SMEM_FLOATS 15792
#define ENC_SMEM_BYTES  (ENC_SMEM_FLOATS * 4)
#define ENC_H2_OFF   0
#define ENC_ENC_OFF  2048

__global__ void __launch_bounds__(256, 3)
enc_kernel(const int* __restrict__ ti, const float* __restrict__ emb,
           const float* __restrict__ w1, const float* __restrict__ b1,
           const float* __restrict__ w2, const float* __restrict__ b2,
           const float* __restrict__ w3, const float* __restrict__ b3,
           const float* __restrict__ cb,
           float* __restrict__ out_feat, float* __restrict__ out_qst,
           float* __restrict__ out_puzz)
{
    extern __shared__ float s[];
    float* SA  = s + ENC_SA;
    float* X   = SA;
    float* H1  = s + ENC_H1;
    float* WT  = s + ENC_WT;
    float* CB  = s + ENC_CB;
    float* DIST= s + ENC_DIST;
    float* BS  = s + ENC_BS;
    float* H2  = SA + ENC_H2_OFF;
    float* ENC = SA + ENC_ENC_OFF;
    __shared__ int   codes_s[30];
    __shared__ float mind_s[30];

    const int tid = threadIdx.x;
    const int b   = blockIdx.x;

    // zero halos; load codebook; stage w1 transposed: WT[(e*3+k)*66 + o] = w1[o*96 + e*3+k]
    for (int i = tid; i < 4224; i += 256) { X[i] = 0.f; H1[i] = 0.f; }
    for (int i = tid; i < 640; i += 256) CB[i] = cb[i];
    for (int i = tid; i < 6144; i += 256) {
        int o = i / 96, r = i - o * 96;
        WT[r * 66 + o] = w1[i];
    }
    if (tid < 64) BS[tid] = b1[tid];
    __syncthreads();

    // gather: X[e][l+1] = emb[ti[l]*32 + e]
    const int* tirow = ti + b * LL;
    for (int i = tid; i < LL * EE; i += 256) {
        int l = i >> 5, e = i & 31;
        X[e * 132 + l + 1] = emb[tirow[l] * EE + e];
    }
    __syncthreads();

    // conv1: X [32][128] pad1 s2 k3 -> H1 [64][64], ReLU.  2o x 8t, 256 threads
    {
        const int o0 = (tid & 31) * 2;
        const int t0 = (tid >> 5) * 8;
        float acc0[8], acc1[8];
        float bb0 = BS[o0], bb1 = BS[o0 + 1];
        #pragma unroll
        for (int u = 0; u < 8; u++) { acc0[u] = bb0; acc1[u] = bb1; }
        for (int e = 0; e < 32; e++) {
            float xv[17];
            const float* xr = &X[e * 132 + 2 * t0];
            #pragma unroll
            for (int u = 0; u < 17; u++) xv[u] = xr[u];
            #pragma unroll
            for (int k = 0; k < 3; k++) {
                float2 w = *(const float2*)&WT[(e * 3 + k) * 66 + o0];
                #pragma unroll
                for (int t = 0; t < 8; t++) {
                    float x = xv[2 * t + k];
                    acc0[t] += w.x * x;
                    acc1[t] += w.y * x;
                }
            }
        }
        #pragma unroll
        for (int t = 0; t < 8; t++) {
            H1[o0 * 66 + t0 + t + 1]       = fmaxf(acc0[t], 0.f);
            H1[(o0 + 1) * 66 + t0 + t + 1] = fmaxf(acc1[t], 0.f);
        }
    }
    __syncthreads();

    // conv2: H1 [64][64] pad1 s2 k3 -> H2 [64][32], ReLU.  2o x 4t, 256 threads, e-halves
    {
        const int o0 = (tid & 31) * 2;
        const int t0 = (tid >> 5) * 4;
        float acc0[4], acc1[4];
        #pragma unroll
        for (int half = 0; half < 2; half++) {
            for (int i = tid; i < 6144; i += 256) {
                int o = i / 96, r = i - o * 96;
                WT[r * 66 + o] = w2[o * 192 + 96 * half + r];
            }
            if (half == 0 && tid < 64) BS[tid] = b2[tid];
            __syncthreads();
            if (half == 0) {
                float bb0 = BS[o0], bb1 = BS[o0 + 1];
                #pragma unroll
                for (int u = 0; u < 4; u++) { acc0[u] = bb0; acc1[u] = bb1; }
            }
            for (int e = 0; e < 32; e++) {
                float xv[9];
                const float* xr = &H1[(half * 32 + e) * 66 + 2 * t0];
                #pragma unroll
                for (int u = 0; u < 9; u++) xv[u] = xr[u];
                #pragma unroll
                for (int k = 0; k < 3; k++) {
                    float2 w = *(const float2*)&WT[(e * 3 + k) * 66 + o0];
                    #pragma unroll
                    for (int t = 0; t < 4; t++) {
                        float x = xv[2 * t + k];
                        acc0[t] += w.x * x;
                        acc1[t] += w.y * x;
                    }
                }
            }
            __syncthreads();
        }
        #pragma unroll
        for (int t = 0; t < 4; t++) {
            H2[o0 * 32 + t0 + t]       = fmaxf(acc0[t], 0.f);
            H2[(o0 + 1) * 32 + t0 + t] = fmaxf(acc1[t], 0.f);
        }
    }
    __syncthreads();

    // conv3: H2 [64][32] pad0 s1 k3 -> ENC [30][64] transposed.  2o x 5t, 192 act, e-halves
    {
        const bool act = tid < 192;
        const int o0 = (tid & 31) * 2;
        const int t0 = (tid >> 5) * 5;
        float acc0[5], acc1[5];
        #pragma unroll
        for (int half = 0; half < 2; half++) {
            for (int i = tid; i < 6144; i += 256) {
                int o = i / 96, r = i - o * 96;
                WT[r * 66 + o] = w3[o * 192 + 96 * half + r];
            }
            if (half == 0 && tid < 64) BS[tid] = b3[tid];
            __syncthreads();
            if (act) {
                if (half == 0) {
                    float bb0 = BS[o0], bb1 = BS[o0 + 1];
                    #pragma unroll
                    for (int u = 0; u < 5; u++) { acc0[u] = bb0; acc1[u] = bb1; }
                }
                for (int e = 0; e < 32; e++) {
                    float xv[7];
                    const float* xr = &H2[(half * 32 + e) * 32 + t0];
                    #pragma unroll
                    for (int u = 0; u < 7; u++) xv[u] = xr[u];
                    #pragma unroll
                    for (int k = 0; k < 3; k++) {
                        float2 w = *(const float2*)&WT[(e * 3 + k) * 66 + o0];
                        #pragma unroll
                        for (int t = 0; t < 5; t++) {
                            float x = xv[t + k];
                            acc0[t] += w.x * x;
                            acc1[t] += w.y * x;
                        }
                    }
                }
            }
            __syncthreads();
        }
        if (act) {
            #pragma unroll
            for (int t = 0; t < 5; t++) {
                ENC[(t0 + t) * 64 + o0]     = acc0[t];
                ENC[(t0 + t) * 64 + o0 + 1] = acc1[t];
            }
        }
    }
    __syncthreads();

    // VQ distances
    for (int idx = tid; idx < 300; idx += 256) {
        int i = idx / 10, c = idx - i * 10;
        const float* fe = &ENC[i * 64];
        const float* cc = &CB[c * 64];
        float acc = 0.f;
        #pragma unroll 8
        for (int d = 0; d < 64; d++) { float df = fe[d] - cc[d]; acc += df * df; }
        DIST[i * 10 + c] = acc;
    }
    __syncthreads();
    if (tid < 30) {
        float mv = DIST[tid * 10]; int mc = 0;
        #pragma unroll
        for (int c = 1; c < 10; c++) {
            float v = DIST[tid * 10 + c];
            if (v < mv) { mv = v; mc = c; }
        }
        codes_s[tid] = mc;
        mind_s[tid] = mv;
        g_codes[b * 30 + tid] = mc;
    }
    __syncthreads();
    if (tid == 0) {
        float acc = 0.f;
        #pragma unroll
        for (int i = 0; i < 30; i++) acc += mind_s[i];
        g_partial[b] = acc;
    }

    // ---- fused broadcast stores: puzzles, features, quantized_st ----
    {
        float* puz = out_puzz + (size_t)b * 900;
        for (int idx = tid; idx < 900; idx += 256) puz[idx] = (float)codes_s[idx / 30];

        const float4* enc4 = (const float4*)ENC;
        const float4* cb4  = (const float4*)CB;
        float4* f4 = (float4*)out_feat + (size_t)b * 14400;
        float4* q4 = (float4*)out_qst  + (size_t)b * 14400;
        #pragma unroll 4
        for (int idx = tid; idx < 14400; idx += 256) {
            int row = idx >> 4;        // i*30 + j
            int q = idx & 15;
            int i = row / 30;
            f4[idx] = enc4[i * 16 + q];
            q4[idx] = cb4[codes_s[i] * 16 + q];
        }
    }
}

// ---------------- Decoder shared layout (floats) ----------------
// REG0 (4608): F [64][36] @0 + G1 [64][36] @2304; later G3 [32][132] aliases it
// G2 (4352): [64][68];  WT (8704 max);  CB (640), BS (64), OB (128)
#define DEC_REG0 0
#define DEC_F    0
#define DEC_G1   2304
#define DEC_G3   0
#define DEC_G2   4608
#define DEC_WT   8960
#define DEC_CB   17664
#define DEC_BS   18304
#define DEC_OB   18368
#define DEC_SMEM_FLOATS 18496
#define DEC_SMEM_BYTES  (DEC_SMEM_FLOATS * 4)

__global__ void __launch_bounds__(256, 3)
dec_kernel(const float* __restrict__ cb,
           const float* __restrict__ dw1, const float* __restrict__ db1,
           const float* __restrict__ dw2, const float* __restrict__ db2,
           const float* __restrict__ dw3, const float* __restrict__ db3,
           const float* __restrict__ ow,  const float* __restrict__ ob,
           float* __restrict__ out_logits)
{
    extern __shared__ float s[];
    float* F  = s + DEC_F;
    float* G1 = s + DEC_G1;
    float* G2 = s + DEC_G2;
    float* G3 = s + DEC_G3;
    float* WT = s + DEC_WT;
    float* CB = s + DEC_CB;
    float* BS = s + DEC_BS;
    float* OB = s + DEC_OB;
    __shared__ int codes_s[30];

    const int tid = threadIdx.x;
    const int b   = blockIdx.x;

    for (int i = tid; i < 4608; i += 256) s[DEC_REG0 + i] = 0.f;
    for (int i = tid; i < 4352; i += 256) G2[i] = 0.f;
    for (int i = tid; i < 640; i += 256) CB[i] = cb[i];
    if (tid < 30) codes_s[tid] = g_codes[b * 30 + tid];
    if (tid < 64) BS[tid] = db1[tid];
    __syncthreads();

    // F[d][i+2] = codebook[code[i]][d]
    for (int idx = tid; idx < 64 * 30; idx += 256) {
        int d = idx / 30, i = idx - d * 30;
        F[d * 36 + i + 2] = CB[codes_s[i] * 64 + d];
    }

    // convT1: F [64][30] s1 p0 k3 -> G1 [64][32], ReLU.  2o x 4t, 256 threads, c-halves
    {
        const int o0 = (tid & 31) * 2;
        const int t0 = (tid >> 5) * 4;
        float ac0[4], ac1[4];
        {
            float bb0 = BS[o0], bb1 = BS[o0 + 1];
            #pragma unroll
            for (int u = 0; u < 4; u++) { ac0[u] = bb0; ac1[u] = bb1; }
        }
        #pragma unroll
        for (int half = 0; half < 2; half++) {
            __syncthreads();
            for (int i = tid; i < 6144; i += 256) {
                int o = i & 63, q = i >> 6;
                int cl = q / 3, k = q - cl * 3;
                WT[q * 66 + o] = dw1[(cl + 32 * half) * 192 + o * 3 + k];
            }
            __syncthreads();
            for (int cl = 0; cl < 32; cl++) {
                float xv[6];
                const float* xr = &F[(half * 32 + cl) * 36 + t0];
                #pragma unroll
                for (int u = 0; u < 6; u++) xv[u] = xr[u];
                #pragma unroll
                for (int k = 0; k < 3; k++) {
                    float2 w = *(const float2*)&WT[(cl * 3 + k) * 66 + o0];
                    #pragma unroll
                    for (int t = 0; t < 4; t++) {
                        float x = xv[t + 2 - k];
                        ac0[t] += w.x * x;
                        ac1[t] += w.y * x;
                    }
                }
            }
        }
        __syncthreads();
        #pragma unroll
        for (int t = 0; t < 4; t++) {
            G1[o0 * 36 + t0 + t + 1]       = fmaxf(ac0[t], 0.f);
            G1[(o0 + 1) * 36 + t0 + t + 1] = fmaxf(ac1[t], 0.f);
        }
    }
    __syncthreads();

    // convT2: G1 [64][32] s2 p1 k4 -> G2 [64][64], ReLU.  2o x 8t, c-halves
    {
        const int oo = (tid & 31) * 2;
        const int tt0 = (tid >> 5) * 8;
        float b20[8], b21[8];
        if (tid < 64) BS[tid] = db2[tid];
        __syncthreads();
        {
            float bb0 = BS[oo], bb1 = BS[oo + 1];
            #pragma unroll
            for (int u = 0; u < 8; u++) { b20[u] = bb0; b21[u] = bb1; }
        }
        #pragma unroll
        for (int half = 0; half < 2; half++) {
            if (half) __syncthreads();
            for (int i = tid; i < 8192; i += 256) {
                int o = i & 63, q = i >> 6;
                int cl = q >> 2, k = q & 3;
                WT[q * 66 + o] = dw2[(cl + 32 * half) * 256 + o * 4 + k];
            }
            __syncthreads();
            for (int cl = 0; cl < 32; cl++) {
                float xv[6];
                const float* xr = &G1[(half * 32 + cl) * 36 + (tt0 >> 1)];
                #pragma unroll
                for (int u = 0; u < 6; u++) xv[u] = xr[u];
                float2 w0 = *(const float2*)&WT[(cl * 4 + 0) * 66 + oo];
                float2 w1 = *(const float2*)&WT[(cl * 4 + 1) * 66 + oo];
                float2 w2 = *(const float2*)&WT[(cl * 4 + 2) * 66 + oo];
                float2 w3 = *(const float2*)&WT[(cl * 4 + 3) * 66 + oo];
                #pragma unroll
                for (int t = 0; t < 8; t++) {
                    int u1 = ((t + 1) >> 1) + 1;
                    float xh = xv[u1], xl = xv[u1 - 1];
                    if (t & 1) {
                        b20[t] += w0.x * xh + w2.x * xl;
                        b21[t] += w0.y * xh + w2.y * xl;
                    } else {
                        b20[t] += w1.x * xh + w3.x * xl;
                        b21[t] += w1.y * xh + w3.y * xl;
                    }
                }
            }
        }
        #pragma unroll
        for (int t = 0; t < 8; t++) {
            G2[oo * 68 + tt0 + t + 1]       = fmaxf(b20[t], 0.f);
            G2[(oo + 1) * 68 + tt0 + t + 1] = fmaxf(b21[t], 0.f);
        }
    }
    __syncthreads();

    // convT3: G2 [64][64] s2 p1 k4 -> G3 [32][128] (aliases F/G1).  2o x 8t
    {
        const int oo = (tid & 15) * 2;
        const int tt0 = (tid >> 4) * 8;
        float b30[8], b31[8];
        for (int i = tid; i < 8192; i += 256) {
            int o = i & 31, q = i >> 5;
            int c = q >> 2, k = q & 3;
            WT[q * 34 + o] = dw3[c * 128 + o * 4 + k];
        }
        if (tid < 32) BS[tid] = db3[tid];
        __syncthreads();
        {
            float bb0 = BS[oo], bb1 = BS[oo + 1];
            #pragma unroll
            for (int u = 0; u < 8; u++) { b30[u] = bb0; b31[u] = bb1; }
        }
        for (int c = 0; c < 64; c++) {
            float xv[6];
            const float* xr = &G2[c * 68 + (tt0 >> 1)];
            #pragma unroll
            for (int u = 0; u < 6; u++) xv[u] = xr[u];
            float2 w0 = *(const float2*)&WT[(c * 4 + 0) * 34 + oo];
            float2 w1 = *(const float2*)&WT[(c * 4 + 1) * 34 + oo];
            float2 w2 = *(const float2*)&WT[(c * 4 + 2) * 34 + oo];
            float2 w3 = *(const float2*)&WT[(c * 4 + 3) * 34 + oo];
            #pragma unroll
            for (int t = 0; t < 8; t++) {
                int u1 = ((t + 1) >> 1) + 1;
                float xh = xv[u1], xl = xv[u1 - 1];
                if (t & 1) {
                    b30[t] += w0.x * xh + w2.x * xl;
                    b31[t] += w0.y * xh + w2.y * xl;
                } else {
                    b30[t] += w1.x * xh + w3.x * xl;
                    b31[t] += w1.y * xh + w3.y * xl;
                }
            }
        }
        __syncthreads();
        #pragma unroll
        for (int t = 0; t < 8; t++) {
            G3[oo * 132 + tt0 + t]       = b30[t];
            G3[(oo + 1) * 132 + tt0 + t] = b31[t];
        }
    }
    __syncthreads();

    // final GEMM: logits[l][v] = sum_e G3[e][l] * ow[v*32+e] + ob[v].  4v x 16l per thread
    {
        for (int i = tid; i < 4096; i += 256) {
            int v = i >> 5, e = i & 31;
            WT[e * 132 + v] = ow[i];
        }
        if (tid < 128) OB[tid] = ob[tid];
        __syncthreads();
        const int v0 = (tid & 31) * 4;
        const int l0 = (tid >> 5) * 16;
        float ga[4][16];
        #pragma unroll
        for (int j = 0; j < 4; j++) {
            float bj = OB[v0 + j];
            #pragma unroll
            for (int u = 0; u < 16; u++) ga[j][u] = bj;
        }
        for (int e = 0; e < 32; e++) {
            float xv[16];
            const float* xr = &G3[e * 132 + l0];
            #pragma unroll
            for (int u = 0; u < 16; u++) xv[u] = xr[u];
            float4 w = *(const float4*)&WT[e * 132 + v0];
            #pragma unroll
            for (int u = 0; u < 16; u++) {
                float x = xv[u];
                ga[0][u] += w.x * x;
                ga[1][u] += w.y * x;
                ga[2][u] += w.z * x;
                ga[3][u] += w.w * x;
            }
        }
        float* outp = out_logits + ((size_t)b * 128 + l0) * 128 + v0;
        #pragma unroll
        for (int u = 0; u < 16; u++) {
            float4 vv = make_float4(ga[0][u], ga[1][u], ga[2][u], ga[3][u]);
            *(float4*)(outp + (size_t)u * 128) = vv;
        }
    }
}

// Deterministic loss reduce
__global__ void loss_kernel(float* __restrict__ out_loss)
{
    __shared__ float sm[256];
    float a = 0.f;
    for (int i = threadIdx.x; i < BB; i += 256) a += g_partial[i];
    sm[threadIdx.x] = a;
    __syncthreads();
    for (int sft = 128; sft > 0; sft >>= 1) {
        if (threadIdx.x < sft) sm[threadIdx.x] += sm[threadIdx.x + sft];
        __syncthreads();
    }
    if (threadIdx.x == 0)
        out_loss[0] = sm[0] * (1.25f / (2048.f * 30.f * 64.f));
}

extern "C" void kernel_launch(void* const* d_in, const int* in_sizes, int n_in,
                              void* d_out, int out_size)
{
    const int*   ti     = (const int*)  d_in[0];
    const float* emb    = (const float*)d_in[1];
    const float* enc_w1 = (const float*)d_in[2];
    const float* enc_b1 = (const float*)d_in[3];
    const float* enc_w2 = (const float*)d_in[4];
    const float* enc_b2 = (const float*)d_in[5];
    const float* enc_w3 = (const float*)d_in[6];
    const float* enc_b3 = (const float*)d_in[7];
    const float* cb     = (const float*)d_in[8];
    const float* dec_w1 = (const float*)d_in[9];
    const float* dec_b1 = (const float*)d_in[10];
    const float* dec_w2 = (const float*)d_in[11];
    const float* dec_b2 = (const float*)d_in[12];
    const float* dec_w3 = (const float*)d_in[13];
    const float* dec_b3 = (const float*)d_in[14];
    const float* out_w  = (const float*)d_in[15];
    const float* out_b  = (const float*)d_in[16];

    float* out        = (float*)d_out;
    float* out_logits = out;
    float* out_puzz   = out + OFF_PUZZ;
    float* out_feat   = out + OFF_FEAT;
    float* out_qst    = out + OFF_QST;
    float* out_loss   = out + OFF_LOSS;

    cudaFuncSetAttribute(enc_kernel, cudaFuncAttributeMaxDynamicSharedMemorySize, ENC_SMEM_BYTES);
    cudaFuncSetAttribute(dec_kernel, cudaFuncAttributeMaxDynamicSharedMemorySize, DEC_SMEM_BYTES);

    enc_kernel<<<BB, 256, ENC_SMEM_BYTES>>>(ti, emb, enc_w1, enc_b1, enc_w2, enc_b2,
                                            enc_w3, enc_b3, cb,
                                            out_feat, out_qst, out_puzz);
    dec_kernel<<<BB, 256, DEC_SMEM_BYTES>>>(cb, dec_w1, dec_b1, dec_w2, dec_b2,
                                            dec_w3, dec_b3, out_w, out_b, out_logits);
    loss_kernel<<<1, 256>>>(out_loss);
}

// round 5
// speedup vs baseline: 2.8541x; 1.0067x over previous
#include <cuda_runtime.h>
#include <cstdint>

// Problem constants
#define BB   2048
#define LL   128
#define VV   128
#define EE   32
#define DD   64
#define NCB  10

// Output layout (concatenated, float32)
#define OFF_PUZZ  33554432
#define OFF_FEAT  35397632
#define OFF_QST   153362432
#define OFF_LOSS  271327232

// Scratch
__device__ int   g_codes[BB * 30];
__device__ float g_partial[BB];

// ---------------- Encoder shared layout (floats) ----------------
// SA  (4224): X [32][132] during gather/conv1; then H2 [64][32] @0 + ENC [30][64] @2048
// H1  (4352): [64][68]  (row padded to 68 for float4-aligned reads)
// WT  (6336): transposed weights [(e*3+k)][66 pad, o fastest]
// CB (640), DIST (304), BS (64)
#define ENC_SA   0
#define ENC_H1   4224
#define ENC_WT   8576
#define ENC_CB   14912
#define ENC_DIST 15552
#define ENC_BS   15856
#define ENC_SMEM_FLOATS 15920
#define ENC_SMEM_BYTES  (ENC_SMEM_FLOATS * 4)
#define ENC_H2_OFF   0
#define ENC_ENC_OFF  2048

__global__ void __launch_bounds__(256, 3)
enc_kernel(const int* __restrict__ ti, const float* __restrict__ emb,
           const float* __restrict__ w1, const float* __restrict__ b1,
           const float* __restrict__ w2, const float* __restrict__ b2,
           const float* __restrict__ w3, const float* __restrict__ b3,
           const float* __restrict__ cb,
           float* __restrict__ out_feat, float* __restrict__ out_qst,
           float* __restrict__ out_puzz)
{
    extern __shared__ float s[];
    float* SA  = s + ENC_SA;
    float* X   = SA;
    float* H1  = s + ENC_H1;
    float* WT  = s + ENC_WT;
    float* CB  = s + ENC_CB;
    float* DIST= s + ENC_DIST;
    float* BS  = s + ENC_BS;
    float* H2  = SA + ENC_H2_OFF;
    float* ENC = SA + ENC_ENC_OFF;
    __shared__ int   codes_s[30];
    __shared__ float mind_s[30];

    const int tid = threadIdx.x;
    const int b   = blockIdx.x;

    // zero halos; load codebook; stage w1 transposed
    for (int i = tid; i < 4224; i += 256) X[i] = 0.f;
    for (int i = tid; i < 4352; i += 256) H1[i] = 0.f;
    for (int i = tid; i < 640; i += 256) CB[i] = cb[i];
    for (int i = tid; i < 6144; i += 256) {
        int o = i / 96, r = i - o * 96;
        WT[r * 66 + o] = w1[i];
    }
    if (tid < 64) BS[tid] = b1[tid];
    __syncthreads();

    // gather: X[e][l+1] = emb[ti[l]*32 + e]
    const int* tirow = ti + b * LL;
    for (int i = tid; i < LL * EE; i += 256) {
        int l = i >> 5, e = i & 31;
        X[e * 132 + l + 1] = emb[tirow[l] * EE + e];
    }
    __syncthreads();

    // conv1: X [32][128] pad1 s2 k3 -> H1 [64][64], ReLU.  2o x 8t, 256 threads
    {
        const int o0 = (tid & 31) * 2;
        const int t0 = (tid >> 5) * 8;      // 2*t0 multiple of 16 -> 16B aligned
        float acc0[8], acc1[8];
        float bb0 = BS[o0], bb1 = BS[o0 + 1];
        #pragma unroll
        for (int u = 0; u < 8; u++) { acc0[u] = bb0; acc1[u] = bb1; }
        for (int e = 0; e < 32; e++) {
            float xv[17];
            const float* xr = &X[e * 132 + 2 * t0];
            #pragma unroll
            for (int u = 0; u < 4; u++) {
                float4 v = *(const float4*)(xr + 4 * u);
                xv[4*u] = v.x; xv[4*u+1] = v.y; xv[4*u+2] = v.z; xv[4*u+3] = v.w;
            }
            xv[16] = xr[16];
            #pragma unroll
            for (int k = 0; k < 3; k++) {
                float2 w = *(const float2*)&WT[(e * 3 + k) * 66 + o0];
                #pragma unroll
                for (int t = 0; t < 8; t++) {
                    float x = xv[2 * t + k];
                    acc0[t] += w.x * x;
                    acc1[t] += w.y * x;
                }
            }
        }
        #pragma unroll
        for (int t = 0; t < 8; t++) {
            H1[o0 * 68 + t0 + t + 1]       = fmaxf(acc0[t], 0.f);
            H1[(o0 + 1) * 68 + t0 + t + 1] = fmaxf(acc1[t], 0.f);
        }
    }
    __syncthreads();

    // conv2: H1 [64][64] pad1 s2 k3 -> H2 [64][32], ReLU.  2o x 4t, 256 threads, e-halves
    {
        const int o0 = (tid & 31) * 2;
        const int t0 = (tid >> 5) * 4;      // 2*t0 multiple of 8 -> 32B aligned
        float acc0[4], acc1[4];
        #pragma unroll
        for (int half = 0; half < 2; half++) {
            for (int i = tid; i < 6144; i += 256) {
                int o = i / 96, r = i - o * 96;
                WT[r * 66 + o] = w2[o * 192 + 96 * half + r];
            }
            if (half == 0 && tid < 64) BS[tid] = b2[tid];
            __syncthreads();
            if (half == 0) {
                float bb0 = BS[o0], bb1 = BS[o0 + 1];
                #pragma unroll
                for (int u = 0; u < 4; u++) { acc0[u] = bb0; acc1[u] = bb1; }
            }
            for (int e = 0; e < 32; e++) {
                float xv[9];
                const float* xr = &H1[(half * 32 + e) * 68 + 2 * t0];
                #pragma unroll
                for (int u = 0; u < 2; u++) {
                    float4 v = *(const float4*)(xr + 4 * u);
                    xv[4*u] = v.x; xv[4*u+1] = v.y; xv[4*u+2] = v.z; xv[4*u+3] = v.w;
                }
                xv[8] = xr[8];
                #pragma unroll
                for (int k = 0; k < 3; k++) {
                    float2 w = *(const float2*)&WT[(e * 3 + k) * 66 + o0];
                    #pragma unroll
                    for (int t = 0; t < 4; t++) {
                        float x = xv[2 * t + k];
                        acc0[t] += w.x * x;
                        acc1[t] += w.y * x;
                    }
                }
            }
            __syncthreads();
        }
        #pragma unroll
        for (int t = 0; t < 4; t++) {
            H2[o0 * 32 + t0 + t]       = fmaxf(acc0[t], 0.f);
            H2[(o0 + 1) * 32 + t0 + t] = fmaxf(acc1[t], 0.f);
        }
    }
    __syncthreads();

    // conv3: H2 [64][32] pad0 s1 k3 -> ENC [30][64] transposed.  2o x 5t, 192 act, e-halves
    {
        const bool act = tid < 192;
        const int o0 = (tid & 31) * 2;
        const int t0 = (tid >> 5) * 5;
        float acc0[5], acc1[5];
        #pragma unroll
        for (int half = 0; half < 2; half++) {
            for (int i = tid; i < 6144; i += 256) {
                int o = i / 96, r = i - o * 96;
                WT[r * 66 + o] = w3[o * 192 + 96 * half + r];
            }
            if (half == 0 && tid < 64) BS[tid] = b3[tid];
            __syncthreads();
            if (act) {
                if (half == 0) {
                    float bb0 = BS[o0], bb1 = BS[o0 + 1];
                    #pragma unroll
                    for (int u = 0; u < 5; u++) { acc0[u] = bb0; acc1[u] = bb1; }
                }
                for (int e = 0; e < 32; e++) {
                    float xv[7];
                    const float* xr = &H2[(half * 32 + e) * 32 + t0];
                    #pragma unroll
                    for (int u = 0; u < 7; u++) xv[u] = xr[u];
                    #pragma unroll
                    for (int k = 0; k < 3; k++) {
                        float2 w = *(const float2*)&WT[(e * 3 + k) * 66 + o0];
                        #pragma unroll
                        for (int t = 0; t < 5; t++) {
                            float x = xv[t + k];
                            acc0[t] += w.x * x;
                            acc1[t] += w.y * x;
                        }
                    }
                }
            }
            __syncthreads();
        }
        if (act) {
            #pragma unroll
            for (int t = 0; t < 5; t++) {
                ENC[(t0 + t) * 64 + o0]     = acc0[t];
                ENC[(t0 + t) * 64 + o0 + 1] = acc1[t];
            }
        }
    }
    __syncthreads();

    // VQ distances
    for (int idx = tid; idx < 300; idx += 256) {
        int i = idx / 10, c = idx - i * 10;
        const float* fe = &ENC[i * 64];
        const float* cc = &CB[c * 64];
        float acc = 0.f;
        #pragma unroll 8
        for (int d = 0; d < 64; d++) { float df = fe[d] - cc[d]; acc += df * df; }
        DIST[i * 10 + c] = acc;
    }
    __syncthreads();
    if (tid < 30) {
        float mv = DIST[tid * 10]; int mc = 0;
        #pragma unroll
        for (int c = 1; c < 10; c++) {
            float v = DIST[tid * 10 + c];
            if (v < mv) { mv = v; mc = c; }
        }
        codes_s[tid] = mc;
        mind_s[tid] = mv;
        g_codes[b * 30 + tid] = mc;
    }
    __syncthreads();
    if (tid == 0) {
        float acc = 0.f;
        #pragma unroll
        for (int i = 0; i < 30; i++) acc += mind_s[i];
        g_partial[b] = acc;
    }

    // ---- fused broadcast stores: register-cached, streaming ----
    {
        float* puz = out_puzz + (size_t)b * 900;
        for (int idx = tid; idx < 900; idx += 256)
            __stcs(&puz[idx], (float)codes_s[idx / 30]);

        const float4* enc4 = (const float4*)ENC;
        const float4* cb4  = (const float4*)CB;
        float4* f4 = (float4*)out_feat + (size_t)b * 14400;
        float4* q4 = (float4*)out_qst  + (size_t)b * 14400;
        const int lane = tid & 31;
        const int wid  = tid >> 5;
        const int q    = lane & 15;
        const int jh   = lane >> 4;          // 0 or 1
        for (int i = wid; i < 30; i += 8) {
            float4 ev = enc4[i * 16 + q];
            float4 cv = cb4[codes_s[i] * 16 + q];
            float4* fb = f4 + i * 480 + jh * 16 + q;
            float4* qb = q4 + i * 480 + jh * 16 + q;
            #pragma unroll
            for (int j = 0; j < 30; j += 2) {     // warp covers j, j+1
                __stcs(fb + j * 16, ev);
                __stcs(qb + j * 16, cv);
            }
        }
    }
}

// ---------------- Decoder shared layout (floats) ----------------
// REG0 (4608): F [64][36] @0 + G1 [64][36] @2304; later G3 [32][132] aliases it
// G2 (4352): [64][68];  WT (8704 max);  CB (640), BS (64), OB (128)
#define DEC_REG0 0
#define DEC_F    0
#define DEC_G1   2304
#define DEC_G3   0
#define DEC_G2   4608
#define DEC_WT   8960
#define DEC_CB   17664
#define DEC_BS   18304
#define DEC_OB   18368
#define DEC_SMEM_FLOATS 18496
#define DEC_SMEM_BYTES  (DEC_SMEM_FLOATS * 4)

__global__ void __launch_bounds__(256, 3)
dec_kernel(const float* __restrict__ cb,
           const float* __restrict__ dw1, const float* __restrict__ db1,
           const float* __restrict__ dw2, const float* __restrict__ db2,
           const float* __restrict__ dw3, const float* __restrict__ db3,
           const float* __restrict__ ow,  const float* __restrict__ ob,
           float* __restrict__ out_logits)
{
    extern __shared__ float s[];
    float* F  = s + DEC_F;
    float* G1 = s + DEC_G1;
    float* G2 = s + DEC_G2;
    float* G3 = s + DEC_G3;
    float* WT = s + DEC_WT;
    float* CB = s + DEC_CB;
    float* BS = s + DEC_BS;
    float* OB = s + DEC_OB;
    __shared__ int codes_s[30];

    const int tid = threadIdx.x;
    const int b   = blockIdx.x;

    for (int i = tid; i < 4608; i += 256) s[DEC_REG0 + i] = 0.f;
    for (int i = tid; i < 4352; i += 256) G2[i] = 0.f;
    for (int i = tid; i < 640; i += 256) CB[i] = cb[i];
    if (tid < 30) codes_s[tid] = g_codes[b * 30 + tid];
    if (tid < 64) BS[tid] = db1[tid];
    __syncthreads();

    // F[d][i+2] = codebook[code[i]][d]
    for (int idx = tid; idx < 64 * 30; idx += 256) {
        int d = idx / 30, i = idx - d * 30;
        F[d * 36 + i + 2] = CB[codes_s[i] * 64 + d];
    }

    // convT1: F [64][30] s1 p0 k3 -> G1 [64][32], ReLU.  2o x 4t, 256 threads, c-halves
    {
        const int o0 = (tid & 31) * 2;
        const int t0 = (tid >> 5) * 4;   // 16B aligned
        float ac0[4], ac1[4];
        {
            float bb0 = BS[o0], bb1 = BS[o0 + 1];
            #pragma unroll
            for (int u = 0; u < 4; u++) { ac0[u] = bb0; ac1[u] = bb1; }
        }
        #pragma unroll
        for (int half = 0; half < 2; half++) {
            __syncthreads();
            for (int i = tid; i < 6144; i += 256) {
                int o = i & 63, q = i >> 6;
                int cl = q / 3, k = q - cl * 3;
                WT[q * 66 + o] = dw1[(cl + 32 * half) * 192 + o * 3 + k];
            }
            __syncthreads();
            for (int cl = 0; cl < 32; cl++) {
                float xv[6];
                const float* xr = &F[(half * 32 + cl) * 36 + t0];
                {
                    float4 v = *(const float4*)xr;
                    float2 v2 = *(const float2*)(xr + 4);
                    xv[0]=v.x; xv[1]=v.y; xv[2]=v.z; xv[3]=v.w; xv[4]=v2.x; xv[5]=v2.y;
                }
                #pragma unroll
                for (int k = 0; k < 3; k++) {
                    float2 w = *(const float2*)&WT[(cl * 3 + k) * 66 + o0];
                    #pragma unroll
                    for (int t = 0; t < 4; t++) {
                        float x = xv[t + 2 - k];
                        ac0[t] += w.x * x;
                        ac1[t] += w.y * x;
                    }
                }
            }
        }
        __syncthreads();
        #pragma unroll
        for (int t = 0; t < 4; t++) {
            G1[o0 * 36 + t0 + t + 1]       = fmaxf(ac0[t], 0.f);
            G1[(o0 + 1) * 36 + t0 + t + 1] = fmaxf(ac1[t], 0.f);
        }
    }
    __syncthreads();

    // convT2: G1 [64][32] s2 p1 k4 -> G2 [64][64], ReLU.  2o x 8t, c-halves
    {
        const int oo = (tid & 31) * 2;
        const int tt0 = (tid >> 5) * 8;
        float b20[8], b21[8];
        if (tid < 64) BS[tid] = db2[tid];
        __syncthreads();
        {
            float bb0 = BS[oo], bb1 = BS[oo + 1];
            #pragma unroll
            for (int u = 0; u < 8; u++) { b20[u] = bb0; b21[u] = bb1; }
        }
        #pragma unroll
        for (int half = 0; half < 2; half++) {
            if (half) __syncthreads();
            for (int i = tid; i < 8192; i += 256) {
                int o = i & 63, q = i >> 6;
                int cl = q >> 2, k = q & 3;
                WT[q * 66 + o] = dw2[(cl + 32 * half) * 256 + o * 4 + k];
            }
            __syncthreads();
            for (int cl = 0; cl < 32; cl++) {
                float xv[6];
                const float* xr = &G1[(half * 32 + cl) * 36 + (tt0 >> 1)];
                {
                    float4 v = *(const float4*)xr;
                    float2 v2 = *(const float2*)(xr + 4);
                    xv[0]=v.x; xv[1]=v.y; xv[2]=v.z; xv[3]=v.w; xv[4]=v2.x; xv[5]=v2.y;
                }
                float2 w0 = *(const float2*)&WT[(cl * 4 + 0) * 66 + oo];
                float2 w1 = *(const float2*)&WT[(cl * 4 + 1) * 66 + oo];
                float2 w2 = *(const float2*)&WT[(cl * 4 + 2) * 66 + oo];
                float2 w3 = *(const float2*)&WT[(cl * 4 + 3) * 66 + oo];
                #pragma unroll
                for (int t = 0; t < 8; t++) {
                    int u1 = ((t + 1) >> 1) + 1;
                    float xh = xv[u1], xl = xv[u1 - 1];
                    if (t & 1) {
                        b20[t] += w0.x * xh + w2.x * xl;
                        b21[t] += w0.y * xh + w2.y * xl;
                    } else {
                        b20[t] += w1.x * xh + w3.x * xl;
                        b21[t] += w1.y * xh + w3.y * xl;
                    }
                }
            }
        }
        #pragma unroll
        for (int t = 0; t < 8; t++) {
            G2[oo * 68 + tt0 + t + 1]       = fmaxf(b20[t], 0.f);
            G2[(oo + 1) * 68 + tt0 + t + 1] = fmaxf(b21[t], 0.f);
        }
    }
    __syncthreads();

    // convT3: G2 [64][64] s2 p1 k4 -> G3 [32][128] (aliases F/G1).  2o x 8t
    {
        const int oo = (tid & 15) * 2;
        const int tt0 = (tid >> 4) * 8;
        float b30[8], b31[8];
        for (int i = tid; i < 8192; i += 256) {
            int o = i & 31, q = i >> 5;
            int c = q >> 2, k = q & 3;
            WT[q * 34 + o] = dw3[c * 128 + o * 4 + k];
        }
        if (tid < 32) BS[tid] = db3[tid];
        __syncthreads();
        {
            float bb0 = BS[oo], bb1 = BS[oo + 1];
            #pragma unroll
            for (int u = 0; u < 8; u++) { b30[u] = bb0; b31[u] = bb1; }
        }
        for (int c = 0; c < 64; c++) {
            float xv[6];
            const float* xr = &G2[c * 68 + (tt0 >> 1)];
            {
                float4 v = *(const float4*)xr;
                float2 v2 = *(const float2*)(xr + 4);
                xv[0]=v.x; xv[1]=v.y; xv[2]=v.z; xv[3]=v.w; xv[4]=v2.x; xv[5]=v2.y;
            }
            float2 w0 = *(const float2*)&WT[(c * 4 + 0) * 34 + oo];
            float2 w1 = *(const float2*)&WT[(c * 4 + 1) * 34 + oo];
            float2 w2 = *(const float2*)&WT[(c * 4 + 2) * 34 + oo];
            float2 w3 = *(const float2*)&WT[(c * 4 + 3) * 34 + oo];
            #pragma unroll
            for (int t = 0; t < 8; t++) {
                int u1 = ((t + 1) >> 1) + 1;
                float xh = xv[u1], xl = xv[u1 - 1];
                if (t & 1) {
                    b30[t] += w0.x * xh + w2.x * xl;
                    b31[t] += w0.y * xh + w2.y * xl;
                } else {
                    b30[t] += w1.x * xh + w3.x * xl;
                    b31[t] += w1.y * xh + w3.y * xl;
                }
            }
        }
        __syncthreads();
        #pragma unroll
        for (int t = 0; t < 8; t++) {
            G3[oo * 132 + tt0 + t]       = b30[t];
            G3[(oo + 1) * 132 + tt0 + t] = b31[t];
        }
    }
    __syncthreads();

    // final GEMM: logits[l][v] = sum_e G3[e][l] * ow[v*32+e] + ob[v].  4v x 16l per thread
    {
        for (int i = tid; i < 4096; i += 256) {
            int v = i >> 5, e = i & 31;
            WT[e * 132 + v] = ow[i];
        }
        if (tid < 128) OB[tid] = ob[tid];
        __syncthreads();
        const int v0 = (tid & 31) * 4;
        const int l0 = (tid >> 5) * 16;   // multiple of 16 -> aligned
        float ga[4][16];
        #pragma unroll
        for (int j = 0; j < 4; j++) {
            float bj = OB[v0 + j];
            #pragma unroll
            for (int u = 0; u < 16; u++) ga[j][u] = bj;
        }
        for (int e = 0; e < 32; e++) {
            float xv[16];
            const float* xr = &G3[e * 132 + l0];
            #pragma unroll
            for (int u = 0; u < 4; u++) {
                float4 v = *(const float4*)(xr + 4 * u);
                xv[4*u] = v.x; xv[4*u+1] = v.y; xv[4*u+2] = v.z; xv[4*u+3] = v.w;
            }
            float4 w = *(const float4*)&WT[e * 132 + v0];
            #pragma unroll
            for (int u = 0; u < 16; u++) {
                float x = xv[u];
                ga[0][u] += w.x * x;
                ga[1][u] += w.y * x;
                ga[2][u] += w.z * x;
                ga[3][u] += w.w * x;
            }
        }
        float* outp = out_logits + ((size_t)b * 128 + l0) * 128 + v0;
        #pragma unroll
        for (int u = 0; u < 16; u++) {
            float4 vv = make_float4(ga[0][u], ga[1][u], ga[2][u], ga[3][u]);
            __stcs((float4*)(outp + (size_t)u * 128), vv);
        }
    }
}

// Deterministic loss reduce
__global__ void loss_kernel(float* __restrict__ out_loss)
{
    __shared__ float sm[256];
    float a = 0.f;
    for (int i = threadIdx.x; i < BB; i += 256) a += g_partial[i];
    sm[threadIdx.x] = a;
    __syncthreads();
    for (int sft = 128; sft > 0; sft >>= 1) {
        if (threadIdx.x < sft) sm[threadIdx.x] += sm[threadIdx.x + sft];
        __syncthreads();
    }
    if (threadIdx.x == 0)
        out_loss[0] = sm[0] * (1.25f / (2048.f * 30.f * 64.f));
}

extern "C" void kernel_launch(void* const* d_in, const int* in_sizes, int n_in,
                              void* d_out, int out_size)
{
    const int*   ti     = (const int*)  d_in[0];
    const float* emb    = (const float*)d_in[1];
    const float* enc_w1 = (const float*)d_in[2];
    const float* enc_b1 = (const float*)d_in[3];
    const float* enc_w2 = (const float*)d_in[4];
    const float* enc_b2 = (const float*)d_in[5];
    const float* enc_w3 = (const float*)d_in[6];
    const float* enc_b3 = (const float*)d_in[7];
    const float* cb     = (const float*)d_in[8];
    const float* dec_w1 = (const float*)d_in[9];
    const float* dec_b1 = (const float*)d_in[10];
    const float* dec_w2 = (const float*)d_in[11];
    const float* dec_b2 = (const float*)d_in[12];
    const float* dec_w3 = (const float*)d_in[13];
    const float* dec_b3 = (const float*)d_in[14];
    const float* out_w  = (const float*)d_in[15];
    const float* out_b  = (const float*)d_in[16];

    float* out        = (float*)d_out;
    float* out_logits = out;
    float* out_puzz   = out + OFF_PUZZ;
    float* out_feat   = out + OFF_FEAT;
    float* out_qst    = out + OFF_QST;
    float* out_loss   = out + OFF_LOSS;

    cudaFuncSetAttribute(enc_kernel, cudaFuncAttributeMaxDynamicSharedMemorySize, ENC_SMEM_BYTES);
    cudaFuncSetAttribute(dec_kernel, cudaFuncAttributeMaxDynamicSharedMemorySize, DEC_SMEM_BYTES);

    enc_kernel<<<BB, 256, ENC_SMEM_BYTES>>>(ti, emb, enc_w1, enc_b1, enc_w2, enc_b2,
                                            enc_w3, enc_b3, cb,
                                            out_feat, out_qst, out_puzz);
    dec_kernel<<<BB, 256, DEC_SMEM_BYTES>>>(cb, dec_w1, dec_b1, dec_w2, dec_b2,
                                            dec_w3, dec_b3, out_w, out_b, out_logits);
    loss_kernel<<<1, 256>>>(out_loss);
}

// round 6
// speedup vs baseline: 2.8935x; 1.0138x over previous
#include <cuda_runtime.h>
#include <cstdint>

// Problem constants
#define BB   2048
#define LL   128
#define VV   128
#define EE   32
#define DD   64
#define NCB  10

// Output layout (concatenated, float32)
#define OFF_PUZZ  33554432
#define OFF_FEAT  35397632
#define OFF_QST   153362432
#define OFF_LOSS  271327232

// Scratch
__device__ float g_partial[BB];

// ---------------- Fused shared layout (floats) ----------------
// A  (4608) @0     : enc: X[32][132](4224) -> H2[64][32]@0 + ENC[30][64]@2048
//                    dec: F[64][36]@0 + G1[64][36]@2304 -> G3[32][132]@0
// B  (4352) @4608  : enc: H1[64][68]   dec: G2[64][68]
// WT (8704) @8960  : weight staging (transposed)
// CB (640)  @17664 ; DIST(304) @18304 ; BS(64) @18608 ; OB(128) @18672
#define SM_A     0
#define SM_B     4608
#define SM_WT    8960
#define SM_CB    17664
#define SM_DIST  18304
#define SM_BS    18608
#define SM_OB    18672
#define SM_FLOATS 18800
#define SM_BYTES  (SM_FLOATS * 4)

#define A_H2   0
#define A_ENC  2048
#define A_F    0
#define A_G1   2304
#define A_G3   0

__global__ void __launch_bounds__(256, 3)
fused_kernel(const int* __restrict__ ti, const float* __restrict__ emb,
             const float* __restrict__ w1, const float* __restrict__ b1,
             const float* __restrict__ w2, const float* __restrict__ b2,
             const float* __restrict__ w3, const float* __restrict__ b3,
             const float* __restrict__ cb,
             const float* __restrict__ dw1, const float* __restrict__ db1,
             const float* __restrict__ dw2, const float* __restrict__ db2,
             const float* __restrict__ dw3, const float* __restrict__ db3,
             const float* __restrict__ ow,  const float* __restrict__ ob,
             float* __restrict__ out_logits,
             float* __restrict__ out_feat, float* __restrict__ out_qst,
             float* __restrict__ out_puzz)
{
    extern __shared__ float s[];
    float* X   = s + SM_A;
    float* H1  = s + SM_B;
    float* WT  = s + SM_WT;
    float* CB  = s + SM_CB;
    float* DIST= s + SM_DIST;
    float* BS  = s + SM_BS;
    float* OB  = s + SM_OB;
    float* H2  = s + SM_A + A_H2;
    float* ENC = s + SM_A + A_ENC;
    float* F   = s + SM_A + A_F;
    float* G1  = s + SM_A + A_G1;
    float* G2  = s + SM_B;
    float* G3  = s + SM_A + A_G3;
    __shared__ int   codes_s[30];
    __shared__ float mind_s[30];

    const int tid = threadIdx.x;
    const int b   = blockIdx.x;

    // ================= ENCODER =================
    for (int i = tid; i < 4224; i += 256) X[i] = 0.f;
    for (int i = tid; i < 4352; i += 256) H1[i] = 0.f;
    for (int i = tid; i < 640; i += 256) CB[i] = cb[i];
    for (int i = tid; i < 6144; i += 256) {
        int o = i / 96, r = i - o * 96;
        WT[r * 66 + o] = w1[i];
    }
    if (tid < 64) BS[tid] = b1[tid];
    __syncthreads();

    // gather: X[e][l+1] = emb[ti[l]*32 + e]
    const int* tirow = ti + b * LL;
    for (int i = tid; i < LL * EE; i += 256) {
        int l = i >> 5, e = i & 31;
        X[e * 132 + l + 1] = emb[tirow[l] * EE + e];
    }
    __syncthreads();

    // conv1: X [32][128] pad1 s2 k3 -> H1 [64][64], ReLU.  2o x 8t
    {
        const int o0 = (tid & 31) * 2;
        const int t0 = (tid >> 5) * 8;
        float acc0[8], acc1[8];
        float bb0 = BS[o0], bb1 = BS[o0 + 1];
        #pragma unroll
        for (int u = 0; u < 8; u++) { acc0[u] = bb0; acc1[u] = bb1; }
        for (int e = 0; e < 32; e++) {
            float xv[17];
            const float* xr = &X[e * 132 + 2 * t0];
            #pragma unroll
            for (int u = 0; u < 4; u++) {
                float4 v = *(const float4*)(xr + 4 * u);
                xv[4*u] = v.x; xv[4*u+1] = v.y; xv[4*u+2] = v.z; xv[4*u+3] = v.w;
            }
            xv[16] = xr[16];
            #pragma unroll
            for (int k = 0; k < 3; k++) {
                float2 w = *(const float2*)&WT[(e * 3 + k) * 66 + o0];
                #pragma unroll
                for (int t = 0; t < 8; t++) {
                    float x = xv[2 * t + k];
                    acc0[t] += w.x * x;
                    acc1[t] += w.y * x;
                }
            }
        }
        #pragma unroll
        for (int t = 0; t < 8; t++) {
            H1[o0 * 68 + t0 + t + 1]       = fmaxf(acc0[t], 0.f);
            H1[(o0 + 1) * 68 + t0 + t + 1] = fmaxf(acc1[t], 0.f);
        }
    }
    __syncthreads();

    // conv2: H1 [64][64] pad1 s2 k3 -> H2 [64][32], ReLU.  2o x 4t, e-halves
    {
        const int o0 = (tid & 31) * 2;
        const int t0 = (tid >> 5) * 4;
        float acc0[4], acc1[4];
        #pragma unroll
        for (int half = 0; half < 2; half++) {
            for (int i = tid; i < 6144; i += 256) {
                int o = i / 96, r = i - o * 96;
                WT[r * 66 + o] = w2[o * 192 + 96 * half + r];
            }
            if (half == 0 && tid < 64) BS[tid] = b2[tid];
            __syncthreads();
            if (half == 0) {
                float bb0 = BS[o0], bb1 = BS[o0 + 1];
                #pragma unroll
                for (int u = 0; u < 4; u++) { acc0[u] = bb0; acc1[u] = bb1; }
            }
            for (int e = 0; e < 32; e++) {
                float xv[9];
                const float* xr = &H1[(half * 32 + e) * 68 + 2 * t0];
                #pragma unroll
                for (int u = 0; u < 2; u++) {
                    float4 v = *(const float4*)(xr + 4 * u);
                    xv[4*u] = v.x; xv[4*u+1] = v.y; xv[4*u+2] = v.z; xv[4*u+3] = v.w;
                }
                xv[8] = xr[8];
                #pragma unroll
                for (int k = 0; k < 3; k++) {
                    float2 w = *(const float2*)&WT[(e * 3 + k) * 66 + o0];
                    #pragma unroll
                    for (int t = 0; t < 4; t++) {
                        float x = xv[2 * t + k];
                        acc0[t] += w.x * x;
                        acc1[t] += w.y * x;
                    }
                }
            }
            __syncthreads();
        }
        #pragma unroll
        for (int t = 0; t < 4; t++) {
            H2[o0 * 32 + t0 + t]       = fmaxf(acc0[t], 0.f);
            H2[(o0 + 1) * 32 + t0 + t] = fmaxf(acc1[t], 0.f);
        }
    }
    __syncthreads();

    // conv3: H2 [64][32] pad0 s1 k3 -> ENC [30][64] transposed.  2o x 5t, 192 act, e-halves
    {
        const bool act = tid < 192;
        const int o0 = (tid & 31) * 2;
        const int t0 = (tid >> 5) * 5;
        float acc0[5], acc1[5];
        #pragma unroll
        for (int half = 0; half < 2; half++) {
            for (int i = tid; i < 6144; i += 256) {
                int o = i / 96, r = i - o * 96;
                WT[r * 66 + o] = w3[o * 192 + 96 * half + r];
            }
            if (half == 0 && tid < 64) BS[tid] = b3[tid];
            __syncthreads();
            if (act) {
                if (half == 0) {
                    float bb0 = BS[o0], bb1 = BS[o0 + 1];
                    #pragma unroll
                    for (int u = 0; u < 5; u++) { acc0[u] = bb0; acc1[u] = bb1; }
                }
                for (int e = 0; e < 32; e++) {
                    float xv[7];
                    const float* xr = &H2[(half * 32 + e) * 32 + t0];
                    #pragma unroll
                    for (int u = 0; u < 7; u++) xv[u] = xr[u];
                    #pragma unroll
                    for (int k = 0; k < 3; k++) {
                        float2 w = *(const float2*)&WT[(e * 3 + k) * 66 + o0];
                        #pragma unroll
                        for (int t = 0; t < 5; t++) {
                            float x = xv[t + k];
                            acc0[t] += w.x * x;
                            acc1[t] += w.y * x;
                        }
                    }
                }
            }
            __syncthreads();
        }
        if (act) {
            #pragma unroll
            for (int t = 0; t < 5; t++) {
                ENC[(t0 + t) * 64 + o0]     = acc0[t];
                ENC[(t0 + t) * 64 + o0 + 1] = acc1[t];
            }
        }
    }
    __syncthreads();

    // VQ distances + argmin
    for (int idx = tid; idx < 300; idx += 256) {
        int i = idx / 10, c = idx - i * 10;
        const float* fe = &ENC[i * 64];
        const float* cc = &CB[c * 64];
        float acc = 0.f;
        #pragma unroll 8
        for (int d = 0; d < 64; d++) { float df = fe[d] - cc[d]; acc += df * df; }
        DIST[i * 10 + c] = acc;
    }
    __syncthreads();
    if (tid < 30) {
        float mv = DIST[tid * 10]; int mc = 0;
        #pragma unroll
        for (int c = 1; c < 10; c++) {
            float v = DIST[tid * 10 + c];
            if (v < mv) { mv = v; mc = c; }
        }
        codes_s[tid] = mc;
        mind_s[tid] = mv;
    }
    __syncthreads();
    if (tid == 0) {
        float acc = 0.f;
        #pragma unroll
        for (int i = 0; i < 30; i++) acc += mind_s[i];
        g_partial[b] = acc;
    }

    // ---- broadcast stores (register-cached, streaming); drain overlaps decoder ----
    {
        float* puz = out_puzz + (size_t)b * 900;
        for (int idx = tid; idx < 900; idx += 256)
            __stcs(&puz[idx], (float)codes_s[idx / 30]);

        const float4* enc4 = (const float4*)ENC;
        const float4* cb4  = (const float4*)CB;
        float4* f4 = (float4*)out_feat + (size_t)b * 14400;
        float4* q4 = (float4*)out_qst  + (size_t)b * 14400;
        const int lane = tid & 31;
        const int wid  = tid >> 5;
        const int q    = lane & 15;
        const int jh   = lane >> 4;
        for (int i = wid; i < 30; i += 8) {
            float4 ev = enc4[i * 16 + q];
            float4 cv = cb4[codes_s[i] * 16 + q];
            float4* fb = f4 + i * 480 + jh * 16 + q;
            float4* qb = q4 + i * 480 + jh * 16 + q;
            #pragma unroll
            for (int j = 0; j < 30; j += 2) {
                __stcs(fb + j * 16, ev);
                __stcs(qb + j * 16, cv);
            }
        }
    }
    __syncthreads();   // smem reads of ENC/CB complete before region reuse

    // ================= DECODER =================
    // zero F/G1 (A 0..4608) and G2 (B); load db1
    for (int i = tid; i < 4608; i += 256) s[SM_A + i] = 0.f;
    for (int i = tid; i < 4352; i += 256) G2[i] = 0.f;
    if (tid < 64) BS[tid] = db1[tid];
    __syncthreads();

    // F[d][i+2] = codebook[code[i]][d]
    for (int idx = tid; idx < 64 * 30; idx += 256) {
        int d = idx / 30, i = idx - d * 30;
        F[d * 36 + i + 2] = CB[codes_s[i] * 64 + d];
    }

    // convT1: F [64][30] s1 p0 k3 -> G1 [64][32], ReLU.  2o x 4t, c-halves
    {
        const int o0 = (tid & 31) * 2;
        const int t0 = (tid >> 5) * 4;
        float ac0[4], ac1[4];
        {
            float bb0 = BS[o0], bb1 = BS[o0 + 1];
            #pragma unroll
            for (int u = 0; u < 4; u++) { ac0[u] = bb0; ac1[u] = bb1; }
        }
        #pragma unroll
        for (int half = 0; half < 2; half++) {
            __syncthreads();
            for (int i = tid; i < 6144; i += 256) {
                int o = i & 63, q = i >> 6;
                int cl = q / 3, k = q - cl * 3;
                WT[q * 66 + o] = dw1[(cl + 32 * half) * 192 + o * 3 + k];
            }
            __syncthreads();
            for (int cl = 0; cl < 32; cl++) {
                float xv[6];
                const float* xr = &F[(half * 32 + cl) * 36 + t0];
                {
                    float4 v = *(const float4*)xr;
                    float2 v2 = *(const float2*)(xr + 4);
                    xv[0]=v.x; xv[1]=v.y; xv[2]=v.z; xv[3]=v.w; xv[4]=v2.x; xv[5]=v2.y;
                }
                #pragma unroll
                for (int k = 0; k < 3; k++) {
                    float2 w = *(const float2*)&WT[(cl * 3 + k) * 66 + o0];
                    #pragma unroll
                    for (int t = 0; t < 4; t++) {
                        float x = xv[t + 2 - k];
                        ac0[t] += w.x * x;
                        ac1[t] += w.y * x;
                    }
                }
            }
        }
        __syncthreads();
        #pragma unroll
        for (int t = 0; t < 4; t++) {
            G1[o0 * 36 + t0 + t + 1]       = fmaxf(ac0[t], 0.f);
            G1[(o0 + 1) * 36 + t0 + t + 1] = fmaxf(ac1[t], 0.f);
        }
    }
    __syncthreads();

    // convT2: G1 [64][32] s2 p1 k4 -> G2 [64][64], ReLU.  2o x 8t, c-halves
    {
        const int oo = (tid & 31) * 2;
        const int tt0 = (tid >> 5) * 8;
        float b20[8], b21[8];
        if (tid < 64) BS[tid] = db2[tid];
        __syncthreads();
        {
            float bb0 = BS[oo], bb1 = BS[oo + 1];
            #pragma unroll
            for (int u = 0; u < 8; u++) { b20[u] = bb0; b21[u] = bb1; }
        }
        #pragma unroll
        for (int half = 0; half < 2; half++) {
            if (half) __syncthreads();
            for (int i = tid; i < 8192; i += 256) {
                int o = i & 63, q = i >> 6;
                int cl = q >> 2, k = q & 3;
                WT[q * 66 + o] = dw2[(cl + 32 * half) * 256 + o * 4 + k];
            }
            __syncthreads();
            for (int cl = 0; cl < 32; cl++) {
                float xv[6];
                const float* xr = &G1[(half * 32 + cl) * 36 + (tt0 >> 1)];
                {
                    float4 v = *(const float4*)xr;
                    float2 v2 = *(const float2*)(xr + 4);
                    xv[0]=v.x; xv[1]=v.y; xv[2]=v.z; xv[3]=v.w; xv[4]=v2.x; xv[5]=v2.y;
                }
                float2 w0 = *(const float2*)&WT[(cl * 4 + 0) * 66 + oo];
                float2 w1 = *(const float2*)&WT[(cl * 4 + 1) * 66 + oo];
                float2 w2 = *(const float2*)&WT[(cl * 4 + 2) * 66 + oo];
                float2 w3 = *(const float2*)&WT[(cl * 4 + 3) * 66 + oo];
                #pragma unroll
                for (int t = 0; t < 8; t++) {
                    int u1 = ((t + 1) >> 1) + 1;
                    float xh = xv[u1], xl = xv[u1 - 1];
                    if (t & 1) {
                        b20[t] += w0.x * xh + w2.x * xl;
                        b21[t] += w0.y * xh + w2.y * xl;
                    } else {
                        b20[t] += w1.x * xh + w3.x * xl;
                        b21[t] += w1.y * xh + w3.y * xl;
                    }
                }
            }
        }
        #pragma unroll
        for (int t = 0; t < 8; t++) {
            G2[oo * 68 + tt0 + t + 1]       = fmaxf(b20[t], 0.f);
            G2[(oo + 1) * 68 + tt0 + t + 1] = fmaxf(b21[t], 0.f);
        }
    }
    __syncthreads();

    // convT3: G2 [64][64] s2 p1 k4 -> G3 [32][128] (aliases F/G1).  2o x 8t
    {
        const int oo = (tid & 15) * 2;
        const int tt0 = (tid >> 4) * 8;
        float b30[8], b31[8];
        for (int i = tid; i < 8192; i += 256) {
            int o = i & 31, q = i >> 5;
            int c = q >> 2, k = q & 3;
            WT[q * 34 + o] = dw3[c * 128 + o * 4 + k];
        }
        if (tid < 32) BS[tid] = db3[tid];
        __syncthreads();
        {
            float bb0 = BS[oo], bb1 = BS[oo + 1];
            #pragma unroll
            for (int u = 0; u < 8; u++) { b30[u] = bb0; b31[u] = bb1; }
        }
        for (int c = 0; c < 64; c++) {
            float xv[6];
            const float* xr = &G2[c * 68 + (tt0 >> 1)];
            {
                float4 v = *(const float4*)xr;
                float2 v2 = *(const float2*)(xr + 4);
                xv[0]=v.x; xv[1]=v.y; xv[2]=v.z; xv[3]=v.w; xv[4]=v2.x; xv[5]=v2.y;
            }
            float2 w0 = *(const float2*)&WT[(c * 4 + 0) * 34 + oo];
            float2 w1 = *(const float2*)&WT[(c * 4 + 1) * 34 + oo];
            float2 w2 = *(const float2*)&WT[(c * 4 + 2) * 34 + oo];
            float2 w3 = *(const float2*)&WT[(c * 4 + 3) * 34 + oo];
            #pragma unroll
            for (int t = 0; t < 8; t++) {
                int u1 = ((t + 1) >> 1) + 1;
                float xh = xv[u1], xl = xv[u1 - 1];
                if (t & 1) {
                    b30[t] += w0.x * xh + w2.x * xl;
                    b31[t] += w0.y * xh + w2.y * xl;
                } else {
                    b30[t] += w1.x * xh + w3.x * xl;
                    b31[t] += w1.y * xh + w3.y * xl;
                }
            }
        }
        __syncthreads();
        #pragma unroll
        for (int t = 0; t < 8; t++) {
            G3[oo * 132 + tt0 + t]       = b30[t];
            G3[(oo + 1) * 132 + tt0 + t] = b31[t];
        }
    }
    __syncthreads();

    // final GEMM: logits[l][v] = sum_e G3[e][l] * ow[v*32+e] + ob[v].  4v x 16l
    {
        for (int i = tid; i < 4096; i += 256) {
            int v = i >> 5, e = i & 31;
            WT[e * 132 + v] = ow[i];
        }
        if (tid < 128) OB[tid] = ob[tid];
        __syncthreads();
        const int v0 = (tid & 31) * 4;
        const int l0 = (tid >> 5) * 16;
        float ga[4][16];
        #pragma unroll
        for (int j = 0; j < 4; j++) {
            float bj = OB[v0 + j];
            #pragma unroll
            for (int u = 0; u < 16; u++) ga[j][u] = bj;
        }
        for (int e = 0; e < 32; e++) {
            float xv[16];
            const float* xr = &G3[e * 132 + l0];
            #pragma unroll
            for (int u = 0; u < 4; u++) {
                float4 v = *(const float4*)(xr + 4 * u);
                xv[4*u] = v.x; xv[4*u+1] = v.y; xv[4*u+2] = v.z; xv[4*u+3] = v.w;
            }
            float4 w = *(const float4*)&WT[e * 132 + v0];
            #pragma unroll
            for (int u = 0; u < 16; u++) {
                float x = xv[u];
                ga[0][u] += w.x * x;
                ga[1][u] += w.y * x;
                ga[2][u] += w.z * x;
                ga[3][u] += w.w * x;
            }
        }
        float* outp = out_logits + ((size_t)b * 128 + l0) * 128 + v0;
        #pragma unroll
        for (int u = 0; u < 16; u++) {
            float4 vv = make_float4(ga[0][u], ga[1][u], ga[2][u], ga[3][u]);
            __stcs((float4*)(outp + (size_t)u * 128), vv);
        }
    }
}

// Deterministic loss reduce
__global__ void loss_kernel(float* __restrict__ out_loss)
{
    __shared__ float sm[256];
    float a = 0.f;
    for (int i = threadIdx.x; i < BB; i += 256) a += g_partial[i];
    sm[threadIdx.x] = a;
    __syncthreads();
    for (int sft = 128; sft > 0; sft >>= 1) {
        if (threadIdx.x < sft) sm[threadIdx.x] += sm[threadIdx.x + sft];
        __syncthreads();
    }
    if (threadIdx.x == 0)
        out_loss[0] = sm[0] * (1.25f / (2048.f * 30.f * 64.f));
}

extern "C" void kernel_launch(void* const* d_in, const int* in_sizes, int n_in,
                              void* d_out, int out_size)
{
    const int*   ti     = (const int*)  d_in[0];
    const float* emb    = (const float*)d_in[1];
    const float* enc_w1 = (const float*)d_in[2];
    const float* enc_b1 = (const float*)d_in[3];
    const float* enc_w2 = (const float*)d_in[4];
    const float* enc_b2 = (const float*)d_in[5];
    const float* enc_w3 = (const float*)d_in[6];
    const float* enc_b3 = (const float*)d_in[7];
    const float* cb     = (const float*)d_in[8];
    const float* dec_w1 = (const float*)d_in[9];
    const float* dec_b1 = (const float*)d_in[10];
    const float* dec_w2 = (const float*)d_in[11];
    const float* dec_b2 = (const float*)d_in[12];
    const float* dec_w3 = (const float*)d_in[13];
    const float* dec_b3 = (const float*)d_in[14];
    const float* out_w  = (const float*)d_in[15];
    const float* out_b  = (const float*)d_in[16];

    float* out        = (float*)d_out;
    float* out_logits = out;
    float* out_puzz   = out + OFF_PUZZ;
    float* out_feat   = out + OFF_FEAT;
    float* out_qst    = out + OFF_QST;
    float* out_loss   = out + OFF_LOSS;

    cudaFuncSetAttribute(fused_kernel, cudaFuncAttributeMaxDynamicSharedMemorySize, SM_BYTES);

    fused_kernel<<<BB, 256, SM_BYTES>>>(ti, emb, enc_w1, enc_b1, enc_w2, enc_b2,
                                        enc_w3, enc_b3, cb,
                                        dec_w1, dec_b1, dec_w2, dec_b2,
                                        dec_w3, dec_b3, out_w, out_b,
                                        out_logits, out_feat, out_qst, out_puzz);
    loss_kernel<<<1, 256>>>(out_loss);
}

// round 7
// speedup vs baseline: 3.0874x; 1.0670x over previous
#include <cuda_runtime.h>
#include <cstdint>

// Problem constants
#define BB   2048
#define LL   128

// Output layout (concatenated, float32)
#define OFF_PUZZ  33554432
#define OFF_FEAT  35397632
#define OFF_QST   153362432
#define OFF_LOSS  271327232

// Scratch
__device__ float g_partial[BB];

// Pre-transposed weights (filled by prep_kernel each launch)
// W1T @0      (6336)  : [(e*3+k)*66 + o], e<32,o<64
// W2T @6336   (12672) : [(e*3+k)*66 + o], e<64,o<64
// W3T @19008  (12672) : same as W2T from w3
// DW1T @31680 (12672) : [(cl*3+k)*66 + o], cl<64,o<64
// DW2T @44352 (16896) : [(cl*4+k)*66 + o], cl<64,o<64
// DW3T @61248 (8704)  : [(c*4+k)*34 + o],  c<64,o<32
// OWT  @69952 (4224)  : [e*132 + v], e<32,v<128
#define GW_W1T   0
#define GW_W2T   6336
#define GW_W3T   19008
#define GW_DW1T  31680
#define GW_DW2T  44352
#define GW_DW3T  61248
#define GW_OWT   69952
__device__ float g_wt[74176];

__global__ void prep_kernel(const float* __restrict__ w1, const float* __restrict__ w2,
                            const float* __restrict__ w3, const float* __restrict__ dw1,
                            const float* __restrict__ dw2, const float* __restrict__ dw3,
                            const float* __restrict__ ow)
{
    const int tid = blockIdx.x * blockDim.x + threadIdx.x;
    const int nt  = gridDim.x * blockDim.x;
    for (int i = tid; i < 6144; i += nt) {
        int o = i / 96, r = i - o * 96;
        g_wt[GW_W1T + r * 66 + o] = w1[i];
    }
    for (int i = tid; i < 12288; i += nt) {
        int o = i / 192, r = i - o * 192;
        g_wt[GW_W2T + r * 66 + o] = w2[i];
    }
    for (int i = tid; i < 12288; i += nt) {
        int o = i / 192, r = i - o * 192;
        g_wt[GW_W3T + r * 66 + o] = w3[i];
    }
    for (int i = tid; i < 12288; i += nt) {
        int q = i >> 6, o = i & 63;
        g_wt[GW_DW1T + q * 66 + o] = dw1[(q / 3) * 192 + o * 3 + (q % 3)];
    }
    for (int i = tid; i < 16384; i += nt) {
        int q = i >> 6, o = i & 63;
        g_wt[GW_DW2T + q * 66 + o] = dw2[(q >> 2) * 256 + o * 4 + (q & 3)];
    }
    for (int i = tid; i < 8192; i += nt) {
        int q = i >> 5, o = i & 31;
        g_wt[GW_DW3T + q * 34 + o] = dw3[(q >> 2) * 128 + o * 4 + (q & 3)];
    }
    for (int i = tid; i < 4096; i += nt) {
        int v = i >> 5, e = i & 31;
        g_wt[GW_OWT + e * 132 + v] = ow[i];
    }
}

// ---------------- Fused shared layout (floats) ----------------
// A  (4608) @0     : enc: X[32][132](4224) -> H2[64][32]@0 + ENC[30][64]@2048
//                    dec: F[64][36]@0 + G1[64][36]@2304 -> G3[32][132]@0
// B  (4352) @4608  : enc: H1[64][68]   dec: G2[64][68]
// WT (4352) @8960  : one staging chunk
// CB (640) @13312 ; DIST(304) @13952 ; BS(64) @14256 ; OB(128) @14320
#define SM_A     0
#define SM_B     4608
#define SM_WT    8960
#define SM_CB    13312
#define SM_DIST  13952
#define SM_BS    14256
#define SM_OB    14320
#define SM_FLOATS 14448
#define SM_BYTES  (SM_FLOATS * 4)

#define A_H2   0
#define A_ENC  2048
#define A_F    0
#define A_G1   2304
#define A_G3   0

__global__ void __launch_bounds__(256, 4)
fused_kernel(const int* __restrict__ ti, const float* __restrict__ emb,
             const float* __restrict__ b1, const float* __restrict__ b2,
             const float* __restrict__ b3, const float* __restrict__ cb,
             const float* __restrict__ db1, const float* __restrict__ db2,
             const float* __restrict__ db3, const float* __restrict__ ob,
             float* __restrict__ out_logits,
             float* __restrict__ out_feat, float* __restrict__ out_qst,
             float* __restrict__ out_puzz)
{
    extern __shared__ float s[];
    float* X   = s + SM_A;
    float* H1  = s + SM_B;
    float* WT  = s + SM_WT;
    float* CB  = s + SM_CB;
    float* DIST= s + SM_DIST;
    float* BS  = s + SM_BS;
    float* OB  = s + SM_OB;
    float* H2  = s + SM_A + A_H2;
    float* ENC = s + SM_A + A_ENC;
    float* F   = s + SM_A + A_F;
    float* G1  = s + SM_A + A_G1;
    float* G2  = s + SM_B;
    float* G3  = s + SM_A + A_G3;
    __shared__ int   codes_s[30];
    __shared__ float mind_s[30];

    const int tid = threadIdx.x;
    const int b   = blockIdx.x;

    // ================= ENCODER =================
    for (int i = tid; i < 4224; i += 256) X[i] = 0.f;
    for (int i = tid; i < 4352; i += 256) H1[i] = 0.f;
    for (int i = tid; i < 640; i += 256) CB[i] = cb[i];
    if (tid < 64) BS[tid] = b1[tid];
    __syncthreads();

    // gather: X[e][l+1] = emb[ti[l]*32 + e]
    const int* tirow = ti + b * LL;
    for (int i = tid; i < LL * 32; i += 256) {
        int l = i >> 5, e = i & 31;
        X[e * 132 + l + 1] = emb[tirow[l] * 32 + e];
    }

    // conv1: X [32][128] pad1 s2 k3 -> H1 [64][64], ReLU.  2o x 8t, chunks of 16 e
    {
        const int o0 = (tid & 31) * 2;
        const int t0 = (tid >> 5) * 8;
        float acc0[8], acc1[8];
        #pragma unroll
        for (int ch = 0; ch < 2; ch++) {
            __syncthreads();
            const float4* src = (const float4*)(g_wt + GW_W1T + ch * 3168);
            for (int i = tid; i < 792; i += 256) ((float4*)WT)[i] = src[i];
            __syncthreads();
            if (ch == 0) {
                float bb0 = BS[o0], bb1 = BS[o0 + 1];
                #pragma unroll
                for (int u = 0; u < 8; u++) { acc0[u] = bb0; acc1[u] = bb1; }
            }
            for (int el = 0; el < 16; el++) {
                float xv[17];
                const float* xr = &X[(ch * 16 + el) * 132 + 2 * t0];
                #pragma unroll
                for (int u = 0; u < 4; u++) {
                    float4 v = *(const float4*)(xr + 4 * u);
                    xv[4*u] = v.x; xv[4*u+1] = v.y; xv[4*u+2] = v.z; xv[4*u+3] = v.w;
                }
                xv[16] = xr[16];
                #pragma unroll
                for (int k = 0; k < 3; k++) {
                    float2 w = *(const float2*)&WT[(el * 3 + k) * 66 + o0];
                    #pragma unroll
                    for (int t = 0; t < 8; t++) {
                        float x = xv[2 * t + k];
                        acc0[t] += w.x * x;
                        acc1[t] += w.y * x;
                    }
                }
            }
        }
        __syncthreads();
        #pragma unroll
        for (int t = 0; t < 8; t++) {
            H1[o0 * 68 + t0 + t + 1]       = fmaxf(acc0[t], 0.f);
            H1[(o0 + 1) * 68 + t0 + t + 1] = fmaxf(acc1[t], 0.f);
        }
    }
    __syncthreads();

    // conv2: H1 [64][64] pad1 s2 k3 -> H2 [64][32], ReLU.  2o x 4t, chunks of 16 e
    {
        const int o0 = (tid & 31) * 2;
        const int t0 = (tid >> 5) * 4;
        float acc0[4], acc1[4];
        #pragma unroll
        for (int ch = 0; ch < 4; ch++) {
            __syncthreads();
            const float4* src = (const float4*)(g_wt + GW_W2T + ch * 3168);
            for (int i = tid; i < 792; i += 256) ((float4*)WT)[i] = src[i];
            if (ch == 0 && tid < 64) BS[tid] = b2[tid];
            __syncthreads();
            if (ch == 0) {
                float bb0 = BS[o0], bb1 = BS[o0 + 1];
                #pragma unroll
                for (int u = 0; u < 4; u++) { acc0[u] = bb0; acc1[u] = bb1; }
            }
            for (int el = 0; el < 16; el++) {
                float xv[9];
                const float* xr = &H1[(ch * 16 + el) * 68 + 2 * t0];
                #pragma unroll
                for (int u = 0; u < 2; u++) {
                    float4 v = *(const float4*)(xr + 4 * u);
                    xv[4*u] = v.x; xv[4*u+1] = v.y; xv[4*u+2] = v.z; xv[4*u+3] = v.w;
                }
                xv[8] = xr[8];
                #pragma unroll
                for (int k = 0; k < 3; k++) {
                    float2 w = *(const float2*)&WT[(el * 3 + k) * 66 + o0];
                    #pragma unroll
                    for (int t = 0; t < 4; t++) {
                        float x = xv[2 * t + k];
                        acc0[t] += w.x * x;
                        acc1[t] += w.y * x;
                    }
                }
            }
        }
        __syncthreads();
        #pragma unroll
        for (int t = 0; t < 4; t++) {
            H2[o0 * 32 + t0 + t]       = fmaxf(acc0[t], 0.f);
            H2[(o0 + 1) * 32 + t0 + t] = fmaxf(acc1[t], 0.f);
        }
    }
    __syncthreads();

    // conv3: H2 [64][32] pad0 s1 k3 -> ENC [30][64] transposed.  2o x 5t, 192 act, chunks of 16 e
    {
        const bool act = tid < 192;
        const int o0 = (tid & 31) * 2;
        const int t0 = (tid >> 5) * 5;
        float acc0[5], acc1[5];
        #pragma unroll
        for (int ch = 0; ch < 4; ch++) {
            __syncthreads();
            const float4* src = (const float4*)(g_wt + GW_W3T + ch * 3168);
            for (int i = tid; i < 792; i += 256) ((float4*)WT)[i] = src[i];
            if (ch == 0 && tid < 64) BS[tid] = b3[tid];
            __syncthreads();
            if (act) {
                if (ch == 0) {
                    float bb0 = BS[o0], bb1 = BS[o0 + 1];
                    #pragma unroll
                    for (int u = 0; u < 5; u++) { acc0[u] = bb0; acc1[u] = bb1; }
                }
                for (int el = 0; el < 16; el++) {
                    float xv[7];
                    const float* xr = &H2[(ch * 16 + el) * 32 + t0];
                    #pragma unroll
                    for (int u = 0; u < 7; u++) xv[u] = xr[u];
                    #pragma unroll
                    for (int k = 0; k < 3; k++) {
                        float2 w = *(const float2*)&WT[(el * 3 + k) * 66 + o0];
                        #pragma unroll
                        for (int t = 0; t < 5; t++) {
                            float x = xv[t + k];
                            acc0[t] += w.x * x;
                            acc1[t] += w.y * x;
                        }
                    }
                }
            }
        }
        __syncthreads();
        if (act) {
            #pragma unroll
            for (int t = 0; t < 5; t++) {
                ENC[(t0 + t) * 64 + o0]     = acc0[t];
                ENC[(t0 + t) * 64 + o0 + 1] = acc1[t];
            }
        }
    }
    __syncthreads();

    // VQ distances + argmin
    for (int idx = tid; idx < 300; idx += 256) {
        int i = idx / 10, c = idx - i * 10;
        const float* fe = &ENC[i * 64];
        const float* cc = &CB[c * 64];
        float acc = 0.f;
        #pragma unroll 8
        for (int d = 0; d < 64; d++) { float df = fe[d] - cc[d]; acc += df * df; }
        DIST[i * 10 + c] = acc;
    }
    __syncthreads();
    if (tid < 30) {
        float mv = DIST[tid * 10]; int mc = 0;
        #pragma unroll
        for (int c = 1; c < 10; c++) {
            float v = DIST[tid * 10 + c];
            if (v < mv) { mv = v; mc = c; }
        }
        codes_s[tid] = mc;
        mind_s[tid] = mv;
    }
    __syncthreads();
    if (tid == 0) {
        float acc = 0.f;
        #pragma unroll
        for (int i = 0; i < 30; i++) acc += mind_s[i];
        g_partial[b] = acc;
    }

    // ---- broadcast stores (register-cached, streaming) ----
    {
        float* puz = out_puzz + (size_t)b * 900;
        for (int idx = tid; idx < 900; idx += 256)
            __stcs(&puz[idx], (float)codes_s[idx / 30]);

        const float4* enc4 = (const float4*)ENC;
        const float4* cb4  = (const float4*)CB;
        float4* f4 = (float4*)out_feat + (size_t)b * 14400;
        float4* q4 = (float4*)out_qst  + (size_t)b * 14400;
        const int lane = tid & 31;
        const int wid  = tid >> 5;
        const int q    = lane & 15;
        const int jh   = lane >> 4;
        for (int i = wid; i < 30; i += 8) {
            float4 ev = enc4[i * 16 + q];
            float4 cv = cb4[codes_s[i] * 16 + q];
            float4* fb = f4 + i * 480 + jh * 16 + q;
            float4* qb = q4 + i * 480 + jh * 16 + q;
            #pragma unroll
            for (int j = 0; j < 30; j += 2) {
                __stcs(fb + j * 16, ev);
                __stcs(qb + j * 16, cv);
            }
        }
    }
    __syncthreads();

    // ================= DECODER =================
    for (int i = tid; i < 4608; i += 256) s[SM_A + i] = 0.f;
    for (int i = tid; i < 4352; i += 256) G2[i] = 0.f;
    if (tid < 64) BS[tid] = db1[tid];
    __syncthreads();

    // F[d][i+2] = codebook[code[i]][d]
    for (int idx = tid; idx < 64 * 30; idx += 256) {
        int d = idx / 30, i = idx - d * 30;
        F[d * 36 + i + 2] = CB[codes_s[i] * 64 + d];
    }

    // convT1: F [64][30] s1 p0 k3 -> G1 [64][32], ReLU.  2o x 4t, chunks of 16 cl
    {
        const int o0 = (tid & 31) * 2;
        const int t0 = (tid >> 5) * 4;
        float ac0[4], ac1[4];
        {
            float bb0 = BS[o0], bb1 = BS[o0 + 1];
            #pragma unroll
            for (int u = 0; u < 4; u++) { ac0[u] = bb0; ac1[u] = bb1; }
        }
        #pragma unroll
        for (int ch = 0; ch < 4; ch++) {
            __syncthreads();
            const float4* src = (const float4*)(g_wt + GW_DW1T + ch * 3168);
            for (int i = tid; i < 792; i += 256) ((float4*)WT)[i] = src[i];
            __syncthreads();
            for (int cl = 0; cl < 16; cl++) {
                float xv[6];
                const float* xr = &F[(ch * 16 + cl) * 36 + t0];
                {
                    float4 v = *(const float4*)xr;
                    float2 v2 = *(const float2*)(xr + 4);
                    xv[0]=v.x; xv[1]=v.y; xv[2]=v.z; xv[3]=v.w; xv[4]=v2.x; xv[5]=v2.y;
                }
                #pragma unroll
                for (int k = 0; k < 3; k++) {
                    float2 w = *(const float2*)&WT[(cl * 3 + k) * 66 + o0];
                    #pragma unroll
                    for (int t = 0; t < 4; t++) {
                        float x = xv[t + 2 - k];
                        ac0[t] += w.x * x;
                        ac1[t] += w.y * x;
                    }
                }
            }
        }
        __syncthreads();
        #pragma unroll
        for (int t = 0; t < 4; t++) {
            G1[o0 * 36 + t0 + t + 1]       = fmaxf(ac0[t], 0.f);
            G1[(o0 + 1) * 36 + t0 + t + 1] = fmaxf(ac1[t], 0.f);
        }
    }
    __syncthreads();

    // convT2: G1 [64][32] s2 p1 k4 -> G2 [64][64], ReLU.  2o x 8t, chunks of 16 cl
    {
        const int oo = (tid & 31) * 2;
        const int tt0 = (tid >> 5) * 8;
        float b20[8], b21[8];
        if (tid < 64) BS[tid] = db2[tid];
        __syncthreads();
        {
            float bb0 = BS[oo], bb1 = BS[oo + 1];
            #pragma unroll
            for (int u = 0; u < 8; u++) { b20[u] = bb0; b21[u] = bb1; }
        }
        #pragma unroll
        for (int ch = 0; ch < 4; ch++) {
            __syncthreads();
            const float4* src = (const float4*)(g_wt + GW_DW2T + ch * 4224);
            for (int i = tid; i < 1056; i += 256) ((float4*)WT)[i] = src[i];
            __syncthreads();
            for (int cl = 0; cl < 16; cl++) {
                float xv[6];
                const float* xr = &G1[(ch * 16 + cl) * 36 + (tt0 >> 1)];
                {
                    float4 v = *(const float4*)xr;
                    float2 v2 = *(const float2*)(xr + 4);
                    xv[0]=v.x; xv[1]=v.y; xv[2]=v.z; xv[3]=v.w; xv[4]=v2.x; xv[5]=v2.y;
                }
                float2 w0 = *(const float2*)&WT[(cl * 4 + 0) * 66 + oo];
                float2 w1 = *(const float2*)&WT[(cl * 4 + 1) * 66 + oo];
                float2 w2 = *(const float2*)&WT[(cl * 4 + 2) * 66 + oo];
                float2 w3 = *(const float2*)&WT[(cl * 4 + 3) * 66 + oo];
                #pragma unroll
                for (int t = 0; t < 8; t++) {
                    int u1 = ((t + 1) >> 1) + 1;
                    float xh = xv[u1], xl = xv[u1 - 1];
                    if (t & 1) {
                        b20[t] += w0.x * xh + w2.x * xl;
                        b21[t] += w0.y * xh + w2.y * xl;
                    } else {
                        b20[t] += w1.x * xh + w3.x * xl;
                        b21[t] += w1.y * xh + w3.y * xl;
                    }
                }
            }
        }
        __syncthreads();
        #pragma unroll
        for (int t = 0; t < 8; t++) {
            G2[oo * 68 + tt0 + t + 1]       = fmaxf(b20[t], 0.f);
            G2[(oo + 1) * 68 + tt0 + t + 1] = fmaxf(b21[t], 0.f);
        }
    }
    __syncthreads();

    // convT3: G2 [64][64] s2 p1 k4 -> G3 [32][128].  2o x 8t, chunks of 32 c
    {
        const int oo = (tid & 15) * 2;
        const int tt0 = (tid >> 4) * 8;
        float b30[8], b31[8];
        if (tid < 32) BS[tid] = db3[tid];
        __syncthreads();
        {
            float bb0 = BS[oo], bb1 = BS[oo + 1];
            #pragma unroll
            for (int u = 0; u < 8; u++) { b30[u] = bb0; b31[u] = bb1; }
        }
        #pragma unroll
        for (int ch = 0; ch < 2; ch++) {
            __syncthreads();
            const float4* src = (const float4*)(g_wt + GW_DW3T + ch * 4352);
            for (int i = tid; i < 1088; i += 256) ((float4*)WT)[i] = src[i];
            __syncthreads();
            for (int cl = 0; cl < 32; cl++) {
                float xv[6];
                const float* xr = &G2[(ch * 32 + cl) * 68 + (tt0 >> 1)];
                {
                    float4 v = *(const float4*)xr;
                    float2 v2 = *(const float2*)(xr + 4);
                    xv[0]=v.x; xv[1]=v.y; xv[2]=v.z; xv[3]=v.w; xv[4]=v2.x; xv[5]=v2.y;
                }
                float2 w0 = *(const float2*)&WT[(cl * 4 + 0) * 34 + oo];
                float2 w1 = *(const float2*)&WT[(cl * 4 + 1) * 34 + oo];
                float2 w2 = *(const float2*)&WT[(cl * 4 + 2) * 34 + oo];
                float2 w3 = *(const float2*)&WT[(cl * 4 + 3) * 34 + oo];
                #pragma unroll
                for (int t = 0; t < 8; t++) {
                    int u1 = ((t + 1) >> 1) + 1;
                    float xh = xv[u1], xl = xv[u1 - 1];
                    if (t & 1) {
                        b30[t] += w0.x * xh + w2.x * xl;
                        b31[t] += w0.y * xh + w2.y * xl;
                    } else {
                        b30[t] += w1.x * xh + w3.x * xl;
                        b31[t] += w1.y * xh + w3.y * xl;
                    }
                }
            }
        }
        __syncthreads();   // G1/F reads (earlier phases) and G2 reads done before aliased G3 writes
        #pragma unroll
        for (int t = 0; t < 8; t++) {
            G3[oo * 132 + tt0 + t]       = b30[t];
            G3[(oo + 1) * 132 + tt0 + t] = b31[t];
        }
    }
    __syncthreads();

    // final GEMM: logits[l][v] = sum_e G3[e][l] * ow[v*32+e] + ob[v].  4v x 8l, two l-passes
    {
        const float4* src = (const float4*)(g_wt + GW_OWT);
        for (int i = tid; i < 1056; i += 256) ((float4*)WT)[i] = src[i];
        if (tid < 128) OB[tid] = ob[tid];
        __syncthreads();
        const int v0 = (tid & 31) * 4;
        const int l0 = (tid >> 5) * 16;
        #pragma unroll
        for (int lh = 0; lh < 2; lh++) {
            const int l = l0 + lh * 8;
            float ga[4][8];
            #pragma unroll
            for (int j = 0; j < 4; j++) {
                float bj = OB[v0 + j];
                #pragma unroll
                for (int u = 0; u < 8; u++) ga[j][u] = bj;
            }
            for (int e = 0; e < 32; e++) {
                float xv[8];
                const float* xr = &G3[e * 132 + l];
                #pragma unroll
                for (int u = 0; u < 2; u++) {
                    float4 v = *(const float4*)(xr + 4 * u);
                    xv[4*u] = v.x; xv[4*u+1] = v.y; xv[4*u+2] = v.z; xv[4*u+3] = v.w;
                }
                float4 w = *(const float4*)&WT[e * 132 + v0];
                #pragma unroll
                for (int u = 0; u < 8; u++) {
                    float x = xv[u];
                    ga[0][u] += w.x * x;
                    ga[1][u] += w.y * x;
                    ga[2][u] += w.z * x;
                    ga[3][u] += w.w * x;
                }
            }
            float* outp = out_logits + ((size_t)b * 128 + l) * 128 + v0;
            #pragma unroll
            for (int u = 0; u < 8; u++) {
                float4 vv = make_float4(ga[0][u], ga[1][u], ga[2][u], ga[3][u]);
                __stcs((float4*)(outp + (size_t)u * 128), vv);
            }
        }
    }
}

// Deterministic loss reduce
__global__ void loss_kernel(float* __restrict__ out_loss)
{
    __shared__ float sm[256];
    float a = 0.f;
    for (int i = threadIdx.x; i < BB; i += 256) a += g_partial[i];
    sm[threadIdx.x] = a;
    __syncthreads();
    for (int sft = 128; sft > 0; sft >>= 1) {
        if (threadIdx.x < sft) sm[threadIdx.x] += sm[threadIdx.x + sft];
        __syncthreads();
    }
    if (threadIdx.x == 0)
        out_loss[0] = sm[0] * (1.25f / (2048.f * 30.f * 64.f));
}

extern "C" void kernel_launch(void* const* d_in, const int* in_sizes, int n_in,
                              void* d_out, int out_size)
{
    const int*   ti     = (const int*)  d_in[0];
    const float* emb    = (const float*)d_in[1];
    const float* enc_w1 = (const float*)d_in[2];
    const float* enc_b1 = (const float*)d_in[3];
    const float* enc_w2 = (const float*)d_in[4];
    const float* enc_b2 = (const float*)d_in[5];
    const float* enc_w3 = (const float*)d_in[6];
    const float* enc_b3 = (const float*)d_in[7];
    const float* cb     = (const float*)d_in[8];
    const float* dec_w1 = (const float*)d_in[9];
    const float* dec_b1 = (const float*)d_in[10];
    const float* dec_w2 = (const float*)d_in[11];
    const float* dec_b2 = (const float*)d_in[12];
    const float* dec_w3 = (const float*)d_in[13];
    const float* dec_b3 = (const float*)d_in[14];
    const float* out_w  = (const float*)d_in[15];
    const float* out_b  = (const float*)d_in[16];

    float* out        = (float*)d_out;
    float* out_logits = out;
    float* out_puzz   = out + OFF_PUZZ;
    float* out_feat   = out + OFF_FEAT;
    float* out_qst    = out + OFF_QST;
    float* out_loss   = out + OFF_LOSS;

    cudaFuncSetAttribute(fused_kernel, cudaFuncAttributeMaxDynamicSharedMemorySize, SM_BYTES);

    prep_kernel<<<64, 256>>>(enc_w1, enc_w2, enc_w3, dec_w1, dec_w2, dec_w3, out_w);
    fused_kernel<<<BB, 256, SM_BYTES>>>(ti, emb, enc_b1, enc_b2, enc_b3, cb,
                                        dec_b1, dec_b2, dec_b3, out_b,
                                        out_logits, out_feat, out_qst, out_puzz);
    loss_kernel<<<1, 256>>>(out_loss);
}